// round 2
// baseline (speedup 1.0000x reference)
#include <cuda_runtime.h>
#include <cuda_bf16.h>
#include <cstddef>

// ---------------------------------------------------------------------------
// GPT-2 style transformer forward, fp32 baseline.
// B=2, M=1024, D=1024, H=16, K=64, L=4, V=50257 (V derived from in_sizes).
// ---------------------------------------------------------------------------

#define Bn 2
#define Mseq 1024
#define Dm 1024
#define Hh 16
#define Kh 64
#define Ll 4
#define NTOK (Bn * Mseq)          // 2048

// Scratch (device globals; allocation-free per harness rules)
__device__ float g_x[NTOK * Dm];          // residual stream        8 MB
__device__ float g_y[NTOK * Dm];          // layernorm out          8 MB
__device__ float g_qkv[NTOK * 3 * Dm];    // qkv                   24 MB
__device__ float g_att[NTOK * Dm];        // attention out          8 MB
__device__ float g_h[NTOK * 4 * Dm];      // MLP hidden            32 MB

// ---------------------------------------------------------------------------
// Embedding: x[b,m,:] = emb[token[b,m],:] + pos_emb[m,:]
// ---------------------------------------------------------------------------
__global__ void embed_kernel(const int* __restrict__ tokens,
                             const float* __restrict__ emb,
                             const float* __restrict__ pos,
                             float* __restrict__ x)
{
    int idx = blockIdx.x * blockDim.x + threadIdx.x;   // over NTOK*256 float4
    int row = idx >> 8;            // token row 0..2047
    int d4  = idx & 255;           // float4 col 0..255
    int m   = row & (Mseq - 1);
    int t   = tokens[row];
    float4 e = ((const float4*)emb)[(size_t)t * 256 + d4];
    float4 p = ((const float4*)pos)[(size_t)m * 256 + d4];
    float4 o;
    o.x = e.x + p.x; o.y = e.y + p.y; o.z = e.z + p.z; o.w = e.w + p.w;
    ((float4*)x)[idx] = o;
}

// ---------------------------------------------------------------------------
// LayerNorm: one block (256 threads) per row of D=1024.
// ---------------------------------------------------------------------------
__device__ __forceinline__ float blockReduceSum(float val)
{
    __shared__ float sh[8];
    __shared__ float tot;
    int lane = threadIdx.x & 31;
    int wid  = threadIdx.x >> 5;
    #pragma unroll
    for (int o = 16; o; o >>= 1) val += __shfl_down_sync(0xffffffffu, val, o);
    if (!lane) sh[wid] = val;
    __syncthreads();
    if (threadIdx.x < 32) {
        float v = (threadIdx.x < 8) ? sh[threadIdx.x] : 0.f;
        #pragma unroll
        for (int o = 4; o; o >>= 1) v += __shfl_down_sync(0xffffffffu, v, o);
        if (!threadIdx.x) tot = v;
    }
    __syncthreads();
    return tot;
}

__global__ void ln_kernel(const float* __restrict__ x, float* __restrict__ y,
                          const float* __restrict__ s, const float* __restrict__ b)
{
    int row = blockIdx.x;
    int tid = threadIdx.x;
    const float* xr = x + (size_t)row * Dm;
    float v[4];
    #pragma unroll
    for (int i = 0; i < 4; i++) v[i] = xr[tid + 256 * i];
    float sum = v[0] + v[1] + v[2] + v[3];
    float mu = blockReduceSum(sum) * (1.f / Dm);
    float sq = 0.f;
    #pragma unroll
    for (int i = 0; i < 4; i++) { float d = v[i] - mu; sq += d * d; }
    float var = blockReduceSum(sq) * (1.f / Dm);
    float rs = rsqrtf(var + 1e-5f);
    float* yr = y + (size_t)row * Dm;
    #pragma unroll
    for (int i = 0; i < 4; i++) {
        int c = tid + 256 * i;
        yr[c] = (v[i] - mu) * rs * s[c] + b[c];
    }
}

// ---------------------------------------------------------------------------
// GELU (tanh approx, GPT-2 "new" GELU)
// ---------------------------------------------------------------------------
__device__ __forceinline__ float gelu_new(float v)
{
    float u = 0.7978845608028654f * (v + 0.044715f * v * v * v);
    return 0.5f * v * (1.f + tanhf(u));
}

// ---------------------------------------------------------------------------
// SGEMM: C[M,N] = A[M,K] @ B[K,N] (+bias) (+gelu) (+residual)
// 128x128 tile, BK=8, 256 threads, 8x8 per thread.
// M multiple of 128; K multiple of 8; N arbitrary (bounds-checked; vectorized
// B loads / C stores only when N % 4 == 0 so row strides keep 16B alignment).
// ---------------------------------------------------------------------------
template <bool BIAS, bool RES, bool GELU>
__global__ __launch_bounds__(256) void sgemm_kernel(
    const float* __restrict__ A, const float* __restrict__ B,
    const float* __restrict__ bias, const float* __restrict__ Rres,
    float* __restrict__ C, int M, int N, int Kd)
{
    __shared__ float As[8][128];
    __shared__ float Bs[8][128];
    const int bm = blockIdx.y * 128, bn = blockIdx.x * 128;
    const int tid = threadIdx.x;
    const int trow = tid >> 4, tcol = tid & 15;

    float acc[8][8];
    #pragma unroll
    for (int i = 0; i < 8; i++)
        #pragma unroll
        for (int j = 0; j < 8; j++) acc[i][j] = 0.f;

    const int arow = tid >> 1, acol = (tid & 1) * 4;
    const int brow = tid >> 5, bcol = (tid & 31) * 4;
    const float* Ap = A + (size_t)(bm + arow) * Kd + acol;
    const float* Bp = B + (size_t)brow * N + bn + bcol;
    const bool n4    = ((N & 3) == 0);
    const bool bvec  = n4 && (bn + 128 <= N);   // alignment requires N%4==0

    for (int k0 = 0; k0 < Kd; k0 += 8) {
        float4 a4 = *(const float4*)Ap;
        float4 b4;
        if (bvec) {
            b4 = *(const float4*)Bp;
        } else {
            b4.x = (bn + bcol + 0 < N) ? Bp[0] : 0.f;
            b4.y = (bn + bcol + 1 < N) ? Bp[1] : 0.f;
            b4.z = (bn + bcol + 2 < N) ? Bp[2] : 0.f;
            b4.w = (bn + bcol + 3 < N) ? Bp[3] : 0.f;
        }
        As[acol + 0][arow] = a4.x;
        As[acol + 1][arow] = a4.y;
        As[acol + 2][arow] = a4.z;
        As[acol + 3][arow] = a4.w;
        *(float4*)&Bs[brow][bcol] = b4;
        __syncthreads();

        #pragma unroll
        for (int k = 0; k < 8; k++) {
            float4 a0 = *(const float4*)&As[k][trow * 8];
            float4 a1 = *(const float4*)&As[k][trow * 8 + 4];
            float4 b0 = *(const float4*)&Bs[k][tcol * 8];
            float4 b1 = *(const float4*)&Bs[k][tcol * 8 + 4];
            float ar[8] = {a0.x, a0.y, a0.z, a0.w, a1.x, a1.y, a1.z, a1.w};
            float br[8] = {b0.x, b0.y, b0.z, b0.w, b1.x, b1.y, b1.z, b1.w};
            #pragma unroll
            for (int i = 0; i < 8; i++)
                #pragma unroll
                for (int j = 0; j < 8; j++)
                    acc[i][j] += ar[i] * br[j];
        }
        __syncthreads();
        Ap += 8;
        Bp += (size_t)8 * N;
    }

    #pragma unroll
    for (int i = 0; i < 8; i++) {
        int row = bm + trow * 8 + i;
        size_t rbase = (size_t)row * N;
        #pragma unroll
        for (int j = 0; j < 8; j += 4) {
            int col = bn + tcol * 8 + j;
            if (n4 && col + 3 < N) {
                float4 v;
                v.x = acc[i][j]; v.y = acc[i][j + 1];
                v.z = acc[i][j + 2]; v.w = acc[i][j + 3];
                if (BIAS) {
                    v.x += bias[col]; v.y += bias[col + 1];
                    v.z += bias[col + 2]; v.w += bias[col + 3];
                }
                if (GELU) {
                    v.x = gelu_new(v.x); v.y = gelu_new(v.y);
                    v.z = gelu_new(v.z); v.w = gelu_new(v.w);
                }
                if (RES) {
                    float4 r = *(const float4*)&Rres[rbase + col];
                    v.x += r.x; v.y += r.y; v.z += r.z; v.w += r.w;
                }
                *(float4*)&C[rbase + col] = v;
            } else {
                #pragma unroll
                for (int jj = j; jj < j + 4; jj++) {
                    int c2 = bn + tcol * 8 + jj;
                    if (c2 < N) {
                        float v = acc[i][jj];
                        if (BIAS) v += bias[c2];
                        if (GELU) v = gelu_new(v);
                        if (RES) v += Rres[rbase + c2];
                        C[rbase + c2] = v;
                    }
                }
            }
        }
    }
}

// ---------------------------------------------------------------------------
// Flash attention (causal). Block = 128 threads = 128 query rows of one
// (b, h, qtile). Per-thread q[64] and o[64] live in registers; K/V tiles of 64
// rows streamed through shared memory. Online softmax (rescale only when the
// running max changes).
// ---------------------------------------------------------------------------
__global__ __launch_bounds__(128) void attn_kernel(const float* __restrict__ qkv,
                                                   float* __restrict__ att)
{
    __shared__ float Ks[64][64];
    __shared__ float Vs[64][64];
    const int qt = blockIdx.x, h = blockIdx.y, b = blockIdx.z;
    const int tid = threadIdx.x;
    const int qrow = qt * 128 + tid;

    const size_t qbase = ((size_t)(b * Mseq + qrow)) * (3 * Dm) + h * (3 * Kh);
    float q[64];
    #pragma unroll
    for (int t = 0; t < 16; t++) {
        float4 v = *(const float4*)&qkv[qbase + t * 4];
        q[t * 4 + 0] = v.x; q[t * 4 + 1] = v.y;
        q[t * 4 + 2] = v.z; q[t * 4 + 3] = v.w;
    }
    float o[64];
    #pragma unroll
    for (int d = 0; d < 64; d++) o[d] = 0.f;
    float m = -1e30f, l = 0.f;

    const int nkt = 2 * qt + 2;
    for (int kt = 0; kt < nkt; kt++) {
        #pragma unroll
        for (int t = 0; t < 8; t++) {
            int idx = tid + t * 128;        // 0..1023
            int j = idx >> 4;
            int c = (idx & 15) * 4;
            size_t src = ((size_t)(b * Mseq + kt * 64 + j)) * (3 * Dm) + h * (3 * Kh);
            *(float4*)&Ks[j][c] = *(const float4*)&qkv[src + 64 + c];
            *(float4*)&Vs[j][c] = *(const float4*)&qkv[src + 128 + c];
        }
        __syncthreads();

        int jmax = qrow - kt * 64;
        if (jmax > 63) jmax = 63;
        for (int j = 0; j <= jmax; j++) {
            float s = 0.f;
            #pragma unroll
            for (int d = 0; d < 64; d++) s += q[d] * Ks[j][d];
            s *= 0.125f;                       // 1/sqrt(64)
            if (s > m) {
                float corr = __expf(m - s);
                l *= corr;
                #pragma unroll
                for (int d = 0; d < 64; d++) o[d] *= corr;
                m = s;
            }
            float p = __expf(s - m);
            l += p;
            #pragma unroll
            for (int d = 0; d < 64; d++) o[d] += p * Vs[j][d];
        }
        __syncthreads();
    }

    float inv = 1.f / l;
    size_t obase = ((size_t)(b * Mseq + qrow)) * Dm + h * Kh;
    #pragma unroll
    for (int t = 0; t < 16; t++) {
        float4 v;
        v.x = o[t * 4 + 0] * inv; v.y = o[t * 4 + 1] * inv;
        v.z = o[t * 4 + 2] * inv; v.w = o[t * 4 + 3] * inv;
        *(float4*)&att[obase + t * 4] = v;
    }
}

// ---------------------------------------------------------------------------
// Host launcher
// ---------------------------------------------------------------------------
extern "C" void kernel_launch(void* const* d_in, const int* in_sizes, int n_in,
                              void* d_out, int out_size)
{
    const int*   tokens = (const int*)  d_in[0];
    const float* emb    = (const float*)d_in[1];
    const float* pos    = (const float*)d_in[2];
    const float* ln1_s  = (const float*)d_in[3];
    const float* ln1_b  = (const float*)d_in[4];
    const float* Pi     = (const float*)d_in[5];
    const float* Po     = (const float*)d_in[6];
    const float* ln2_s  = (const float*)d_in[7];
    const float* ln2_b  = (const float*)d_in[8];
    const float* W1     = (const float*)d_in[9];
    const float* b1     = (const float*)d_in[10];
    const float* W2     = (const float*)d_in[11];
    const float* b2     = (const float*)d_in[12];
    const float* lnf_s  = (const float*)d_in[13];
    const float* lnf_b  = (const float*)d_in[14];
    const float* Wh     = (const float*)d_in[15];
    const float* bh     = (const float*)d_in[16];
    float* out = (float*)d_out;

    const int V = in_sizes[16];   // bh element count = vocab size

    float *x, *y, *qkv, *att, *hbuf;
    cudaGetSymbolAddress((void**)&x,    g_x);
    cudaGetSymbolAddress((void**)&y,    g_y);
    cudaGetSymbolAddress((void**)&qkv,  g_qkv);
    cudaGetSymbolAddress((void**)&att,  g_att);
    cudaGetSymbolAddress((void**)&hbuf, g_h);

    // Embedding
    embed_kernel<<<NTOK, 256>>>(tokens, emb, pos, x);

    for (int l = 0; l < Ll; l++) {
        const float* pi  = Pi + (size_t)l * Dm * 3 * Dm;
        const float* po  = Po + (size_t)l * Dm * Dm;
        const float* w1  = W1 + (size_t)l * Dm * 4 * Dm;
        const float* w2  = W2 + (size_t)l * 4 * Dm * Dm;
        const float* bb1 = b1 + (size_t)l * 4 * Dm;
        const float* bb2 = b2 + (size_t)l * Dm;

        // ln1
        ln_kernel<<<NTOK, 256>>>(x, y, ln1_s + l * Dm, ln1_b + l * Dm);
        // qkv = ln1 @ Pi
        sgemm_kernel<false, false, false><<<dim3(3 * Dm / 128, NTOK / 128), 256>>>(
            y, pi, nullptr, nullptr, qkv, NTOK, 3 * Dm, Dm);
        // attention
        attn_kernel<<<dim3(Mseq / 128, Hh, Bn), 128>>>(qkv, att);
        // x = x + att @ Po
        sgemm_kernel<false, true, false><<<dim3(Dm / 128, NTOK / 128), 256>>>(
            att, po, nullptr, x, x, NTOK, Dm, Dm);
        // ln2
        ln_kernel<<<NTOK, 256>>>(x, y, ln2_s + l * Dm, ln2_b + l * Dm);
        // h = gelu(ln2 @ W1 + b1)
        sgemm_kernel<true, false, true><<<dim3(4 * Dm / 128, NTOK / 128), 256>>>(
            y, w1, bb1, nullptr, hbuf, NTOK, 4 * Dm, Dm);
        // x = x + (h @ W2 + b2)
        sgemm_kernel<true, true, false><<<dim3(Dm / 128, NTOK / 128), 256>>>(
            hbuf, w2, bb2, x, x, NTOK, Dm, 4 * Dm);
    }

    // final layernorm + LM head
    ln_kernel<<<NTOK, 256>>>(x, y, lnf_s, lnf_b);
    sgemm_kernel<true, false, false><<<dim3((V + 127) / 128, NTOK / 128), 256>>>(
        y, Wh, bh, nullptr, out, NTOK, V, Dm);
}

// round 4
// speedup vs baseline: 2.4987x; 2.4987x over previous
#include <cuda_runtime.h>
#include <cuda_bf16.h>
#include <cstdint>
#include <cstddef>

// ---------------------------------------------------------------------------
// GPT-2 forward on GB300 (sm_103 base target): split-bf16 HMMA (mma.sync)
// GEMMs + fp32 flash attention.
// B=2, M=1024, D=1024, H=16, K=64, L=4, V=50257.
// ---------------------------------------------------------------------------

#define Bn 2
#define Mseq 1024
#define Dm 1024
#define Hh 16
#define Ll 4
#define NTOK 2048
#define VPAD 50304            // 50257 padded to multiple of 128

// ------------------------------- scratch ----------------------------------
__device__ float g_x[NTOK * Dm];                      // residual (fp32)
__device__ float g_qkv[NTOK * 3 * Dm];                // qkv (fp32)
__device__ __nv_bfloat16 g_yh[NTOK * Dm], g_yl[NTOK * Dm];        // LN out split
__device__ __nv_bfloat16 g_ah[NTOK * Dm], g_al[NTOK * Dm];        // attn out split
__device__ __nv_bfloat16 g_hh[NTOK * 4 * Dm], g_hl[NTOK * 4 * Dm];// MLP hidden split
// transposed+split weights: [N][K] K-major
__device__ __nv_bfloat16 g_PiTh[Ll * 3 * Dm * Dm], g_PiTl[Ll * 3 * Dm * Dm];
__device__ __nv_bfloat16 g_PoTh[Ll * Dm * Dm],     g_PoTl[Ll * Dm * Dm];
__device__ __nv_bfloat16 g_W1Th[Ll * 4 * Dm * Dm], g_W1Tl[Ll * 4 * Dm * Dm];
__device__ __nv_bfloat16 g_W2Th[Ll * 4 * Dm * Dm], g_W2Tl[Ll * 4 * Dm * Dm];
__device__ __nv_bfloat16 g_WhTh[(size_t)VPAD * Dm], g_WhTl[(size_t)VPAD * Dm];

// ----------------------------- PTX helpers --------------------------------
__device__ __forceinline__ void ldsm4(uint32_t& r0, uint32_t& r1,
                                      uint32_t& r2, uint32_t& r3, uint32_t addr)
{
    asm volatile("ldmatrix.sync.aligned.m8n8.x4.shared.b16 {%0,%1,%2,%3}, [%4];"
                 : "=r"(r0), "=r"(r1), "=r"(r2), "=r"(r3) : "r"(addr));
}
__device__ __forceinline__ void mma16816(float* d, const uint32_t* a,
                                         uint32_t b0, uint32_t b1)
{
    asm volatile("mma.sync.aligned.m16n8k16.row.col.f32.bf16.bf16.f32 "
                 "{%0,%1,%2,%3}, {%4,%5,%6,%7}, {%8,%9}, {%0,%1,%2,%3};"
                 : "+f"(d[0]), "+f"(d[1]), "+f"(d[2]), "+f"(d[3])
                 : "r"(a[0]), "r"(a[1]), "r"(a[2]), "r"(a[3]), "r"(b0), "r"(b1));
}
__device__ __forceinline__ void cp16(uint32_t sdst, const void* gsrc)
{
    asm volatile("cp.async.cg.shared.global [%0], [%1], 16;"
                 :: "r"(sdst), "l"(gsrc));
}
__device__ __forceinline__ void cp_commit() {
    asm volatile("cp.async.commit_group;");
}

// ---------------------------------------------------------------------------
// Embedding
// ---------------------------------------------------------------------------
__global__ void embed_kernel(const int* __restrict__ tokens,
                             const float* __restrict__ emb,
                             const float* __restrict__ pos,
                             float* __restrict__ x)
{
    int idx = blockIdx.x * blockDim.x + threadIdx.x;
    int row = idx >> 8;
    int d4  = idx & 255;
    int m   = row & (Mseq - 1);
    int t   = tokens[row];
    float4 e = ((const float4*)emb)[(size_t)t * 256 + d4];
    float4 p = ((const float4*)pos)[(size_t)m * 256 + d4];
    float4 o;
    o.x = e.x + p.x; o.y = e.y + p.y; o.z = e.z + p.z; o.w = e.w + p.w;
    ((float4*)x)[idx] = o;
}

// ---------------------------------------------------------------------------
// Transpose + split: W[K,N] fp32 -> Th/Tl [Nrows][K] bf16 (rows >= N zeroed)
// grid = (rowsOut/32, K/32), block (32,8)
// ---------------------------------------------------------------------------
__global__ void convT_kernel(const float* __restrict__ W,
                             __nv_bfloat16* __restrict__ Th,
                             __nv_bfloat16* __restrict__ Tl,
                             int K, int N)
{
    __shared__ float t[32][33];
    int n0 = blockIdx.x * 32, k0 = blockIdx.y * 32;
    int tx = threadIdx.x, ty = threadIdx.y;
    #pragma unroll
    for (int i = 0; i < 32; i += 8) {
        int k = k0 + ty + i, n = n0 + tx;
        t[ty + i][tx] = (n < N) ? W[(size_t)k * N + n] : 0.f;
    }
    __syncthreads();
    #pragma unroll
    for (int i = 0; i < 32; i += 8) {
        int n = n0 + ty + i, k = k0 + tx;
        float v = t[tx][ty + i];
        __nv_bfloat16 h = __float2bfloat16(v);
        Th[(size_t)n * K + k] = h;
        Tl[(size_t)n * K + k] = __float2bfloat16(v - __bfloat162float(h));
    }
}

// ---------------------------------------------------------------------------
// LayerNorm -> split bf16
// ---------------------------------------------------------------------------
__device__ __forceinline__ float blockReduceSum(float val)
{
    __shared__ float sh[8];
    __shared__ float tot;
    int lane = threadIdx.x & 31, wid = threadIdx.x >> 5;
    #pragma unroll
    for (int o = 16; o; o >>= 1) val += __shfl_down_sync(0xffffffffu, val, o);
    if (!lane) sh[wid] = val;
    __syncthreads();
    if (threadIdx.x < 32) {
        float v = (threadIdx.x < 8) ? sh[threadIdx.x] : 0.f;
        #pragma unroll
        for (int o = 4; o; o >>= 1) v += __shfl_down_sync(0xffffffffu, v, o);
        if (!threadIdx.x) tot = v;
    }
    __syncthreads();
    return tot;
}

__global__ void ln_kernel(const float* __restrict__ x,
                          __nv_bfloat16* __restrict__ yh, __nv_bfloat16* __restrict__ yl,
                          const float* __restrict__ s, const float* __restrict__ b)
{
    int row = blockIdx.x, tid = threadIdx.x;
    const float* xr = x + (size_t)row * Dm;
    float v[4];
    #pragma unroll
    for (int i = 0; i < 4; i++) v[i] = xr[tid + 256 * i];
    float mu = blockReduceSum(v[0] + v[1] + v[2] + v[3]) * (1.f / Dm);
    float sq = 0.f;
    #pragma unroll
    for (int i = 0; i < 4; i++) { float d = v[i] - mu; sq += d * d; }
    float var = blockReduceSum(sq) * (1.f / Dm);
    float rs = rsqrtf(var + 1e-5f);
    #pragma unroll
    for (int i = 0; i < 4; i++) {
        int c = tid + 256 * i;
        float val = (v[i] - mu) * rs * s[c] + b[c];
        __nv_bfloat16 h = __float2bfloat16(val);
        yh[(size_t)row * Dm + c] = h;
        yl[(size_t)row * Dm + c] = __float2bfloat16(val - __bfloat162float(h));
    }
}

__device__ __forceinline__ float gelu_new(float v)
{
    float u = 0.7978845608028654f * (v + 0.044715f * v * v * v);
    return 0.5f * v * (1.f + tanhf(u));
}

// ---------------------------------------------------------------------------
// Split-bf16 HMMA GEMM: C[M,N] = (Ah+Al)[M,K] @ (Bh+Bl)[N,K]^T
// CTA tile 128x128, BK=32, 256 threads (8 warps, warp tile 64x32),
// cp.async double-buffered SMEM, ldmatrix fragments, 3-pass accumulation.
// ---------------------------------------------------------------------------
#define LDB 80                  // padded row pitch in bytes (32 bf16 -> 80B)
#define MATB (128 * LDB)        // 10240 bytes per matrix
#define STG  (4 * MATB)         // 40960 per stage
#define SMEM_GEMM (2 * STG)     // 81920

template <bool BIAS, bool RES, bool GELU, bool OUTF32, bool SPLIT>
__global__ __launch_bounds__(256) void gemm_hmma(
    const __nv_bfloat16* __restrict__ Ah, const __nv_bfloat16* __restrict__ Al,
    const __nv_bfloat16* __restrict__ Bh, const __nv_bfloat16* __restrict__ Bl,
    const float* __restrict__ bias, const float* __restrict__ Res,
    float* __restrict__ C, __nv_bfloat16* __restrict__ Ch,
    __nv_bfloat16* __restrict__ Cl, int N, int K)
{
    extern __shared__ char smem[];
    const uint32_t sb = (uint32_t)__cvta_generic_to_shared(smem);
    const int tid  = threadIdx.x;
    const int lane = tid & 31;
    const int wid  = tid >> 5;
    const int bm = blockIdx.x * 128;
    const int bn = blockIdx.y * 128;
    const int wm = (wid & 1) * 64;        // warp m offset within tile
    const int wn = (wid >> 1) * 32;       // warp n offset within tile

    float acc[4][4][4];
    #pragma unroll
    for (int i = 0; i < 4; i++)
        #pragma unroll
        for (int j = 0; j < 4; j++)
            #pragma unroll
            for (int k = 0; k < 4; k++) acc[i][j][k] = 0.f;

    // ---- async stage loader: 8 cp.async of 16B per thread ----
    auto load_stage = [&](int c, int s) {
        const int kc = c * 32;
        const uint32_t st = sb + s * STG;
        #pragma unroll
        for (int i = 0; i < 2; i++) {
            int idx = tid + i * 256;          // 0..511
            int r = idx >> 2, q = idx & 3;
            uint32_t so = st + r * LDB + q * 16;
            size_t ga = (size_t)(bm + r) * K + kc + q * 8;
            cp16(so,            Ah + ga);
            cp16(so + MATB,     Al + ga);
            size_t gb = (size_t)(bn + r) * K + kc + q * 8;
            cp16(so + 2 * MATB, Bh + gb);
            cp16(so + 3 * MATB, Bl + gb);
        }
        cp_commit();
    };

    const int nk = K / 32;
    load_stage(0, 0);

    const int lr  = lane & 15;
    const int kc2 = (lane >> 4) << 3;      // 0 or 8 (elems)

    for (int c = 0; c < nk; c++) {
        const int s = c & 1;
        if (c + 1 < nk) {
            load_stage(c + 1, s ^ 1);
            asm volatile("cp.async.wait_group 1;");
        } else {
            asm volatile("cp.async.wait_group 0;");
        }
        __syncthreads();

        const uint32_t st = sb + s * STG;
        #pragma unroll
        for (int ks = 0; ks < 2; ks++) {
            const uint32_t ao = st + (wm + lr) * LDB + (ks * 16 + kc2) * 2;
            const uint32_t bo = st + 2 * MATB + (wn + lr) * LDB + (ks * 16 + kc2) * 2;
            uint32_t ah[4][4], al[4][4], bh[2][4], bl[2][4];
            #pragma unroll
            for (int mt = 0; mt < 4; mt++)
                ldsm4(ah[mt][0], ah[mt][1], ah[mt][2], ah[mt][3], ao + mt * 16 * LDB);
            #pragma unroll
            for (int mt = 0; mt < 4; mt++)
                ldsm4(al[mt][0], al[mt][1], al[mt][2], al[mt][3],
                      ao + MATB + mt * 16 * LDB);
            #pragma unroll
            for (int g = 0; g < 2; g++)
                ldsm4(bh[g][0], bh[g][1], bh[g][2], bh[g][3], bo + g * 16 * LDB);
            #pragma unroll
            for (int g = 0; g < 2; g++)
                ldsm4(bl[g][0], bl[g][1], bl[g][2], bl[g][3],
                      bo + MATB + g * 16 * LDB);

            #pragma unroll
            for (int mt = 0; mt < 4; mt++)
                #pragma unroll
                for (int nt = 0; nt < 4; nt++) {
                    int g = nt >> 1, h = nt & 1;
                    mma16816(acc[mt][nt], ah[mt], bh[g][h], bh[g][2 + h]);
                    mma16816(acc[mt][nt], ah[mt], bl[g][h], bl[g][2 + h]);
                    mma16816(acc[mt][nt], al[mt], bh[g][h], bh[g][2 + h]);
                }
        }
        __syncthreads();
    }

    // ------------------------------ epilogue -------------------------------
    const bool headN = (N & 1) != 0;
    #pragma unroll
    for (int mt = 0; mt < 4; mt++) {
        #pragma unroll
        for (int nt = 0; nt < 4; nt++) {
            int row0 = bm + wm + mt * 16 + (lane >> 2);
            int col  = bn + wn + nt * 8 + (lane & 3) * 2;
            #pragma unroll
            for (int half = 0; half < 2; half++) {
                int row = row0 + half * 8;
                float v0 = acc[mt][nt][half * 2];
                float v1 = acc[mt][nt][half * 2 + 1];
                if (!headN) {
                    size_t base = (size_t)row * N + col;
                    if (BIAS) { v0 += bias[col]; v1 += bias[col + 1]; }
                    if (GELU) { v0 = gelu_new(v0); v1 = gelu_new(v1); }
                    if (RES) {
                        float2 r = *(const float2*)&Res[base];
                        v0 += r.x; v1 += r.y;
                    }
                    if (OUTF32) {
                        float2 o; o.x = v0; o.y = v1;
                        *(float2*)&C[base] = o;
                    }
                    if (SPLIT) {
                        __nv_bfloat16 h0 = __float2bfloat16(v0);
                        __nv_bfloat16 h1 = __float2bfloat16(v1);
                        __nv_bfloat162 hp; hp.x = h0; hp.y = h1;
                        __nv_bfloat162 lp;
                        lp.x = __float2bfloat16(v0 - __bfloat162float(h0));
                        lp.y = __float2bfloat16(v1 - __bfloat162float(h1));
                        *(__nv_bfloat162*)&Ch[base] = hp;
                        *(__nv_bfloat162*)&Cl[base] = lp;
                    }
                } else {
                    // LM head: scalar guarded stores (N odd)
                    size_t rb = (size_t)row * N;
                    if (col < N) {
                        float v = v0;
                        if (BIAS) v += bias[col];
                        C[rb + col] = v;
                    }
                    if (col + 1 < N) {
                        float v = v1;
                        if (BIAS) v += bias[col + 1];
                        C[rb + col + 1] = v;
                    }
                }
            }
        }
    }
}

// ---------------------------------------------------------------------------
// Flash attention (fp32, causal), split-bf16 output
// ---------------------------------------------------------------------------
__global__ __launch_bounds__(128) void attn_kernel(const float* __restrict__ qkv,
                                                   __nv_bfloat16* __restrict__ ah,
                                                   __nv_bfloat16* __restrict__ al)
{
    __shared__ float Ks[64][64];
    __shared__ float Vs[64][64];
    const int qt = blockIdx.x, h = blockIdx.y, b = blockIdx.z;
    const int tid = threadIdx.x;
    const int qrow = qt * 128 + tid;

    const size_t qbase = ((size_t)(b * Mseq + qrow)) * (3 * Dm) + h * 192;
    float q[64];
    #pragma unroll
    for (int t = 0; t < 16; t++) {
        float4 v = *(const float4*)&qkv[qbase + t * 4];
        q[t * 4 + 0] = v.x; q[t * 4 + 1] = v.y; q[t * 4 + 2] = v.z; q[t * 4 + 3] = v.w;
    }
    float o[64];
    #pragma unroll
    for (int d = 0; d < 64; d++) o[d] = 0.f;
    float m = -1e30f, l = 0.f;

    const int nkt = 2 * qt + 2;
    for (int kt = 0; kt < nkt; kt++) {
        #pragma unroll
        for (int t = 0; t < 8; t++) {
            int idx = tid + t * 128;
            int j = idx >> 4, c = (idx & 15) * 4;
            size_t src = ((size_t)(b * Mseq + kt * 64 + j)) * (3 * Dm) + h * 192;
            *(float4*)&Ks[j][c] = *(const float4*)&qkv[src + 64 + c];
            *(float4*)&Vs[j][c] = *(const float4*)&qkv[src + 128 + c];
        }
        __syncthreads();

        int jmax = qrow - kt * 64;
        if (jmax > 63) jmax = 63;
        for (int j = 0; j <= jmax; j++) {
            float s0 = 0.f, s1 = 0.f, s2 = 0.f, s3 = 0.f;
            #pragma unroll
            for (int d = 0; d < 64; d += 4) {
                float4 kv = *(const float4*)&Ks[j][d];
                s0 += q[d] * kv.x; s1 += q[d + 1] * kv.y;
                s2 += q[d + 2] * kv.z; s3 += q[d + 3] * kv.w;
            }
            float s = ((s0 + s1) + (s2 + s3)) * 0.125f;
            if (s > m) {
                float corr = __expf(m - s);
                l *= corr;
                #pragma unroll
                for (int d = 0; d < 64; d++) o[d] *= corr;
                m = s;
            }
            float p = __expf(s - m);
            l += p;
            #pragma unroll
            for (int d = 0; d < 64; d += 4) {
                float4 vv = *(const float4*)&Vs[j][d];
                o[d] += p * vv.x; o[d + 1] += p * vv.y;
                o[d + 2] += p * vv.z; o[d + 3] += p * vv.w;
            }
        }
        __syncthreads();
    }

    float inv = 1.f / l;
    size_t obase = ((size_t)(b * Mseq + qrow)) * Dm + h * 64;
    #pragma unroll
    for (int d = 0; d < 64; d += 2) {
        float v0 = o[d] * inv, v1 = o[d + 1] * inv;
        __nv_bfloat16 h0 = __float2bfloat16(v0), h1 = __float2bfloat16(v1);
        __nv_bfloat162 hp; hp.x = h0; hp.y = h1;
        __nv_bfloat162 lp;
        lp.x = __float2bfloat16(v0 - __bfloat162float(h0));
        lp.y = __float2bfloat16(v1 - __bfloat162float(h1));
        *(__nv_bfloat162*)&ah[obase + d] = hp;
        *(__nv_bfloat162*)&al[obase + d] = lp;
    }
}

// ---------------------------------------------------------------------------
// Host launcher
// ---------------------------------------------------------------------------
extern "C" void kernel_launch(void* const* d_in, const int* in_sizes, int n_in,
                              void* d_out, int out_size)
{
    const int*   tokens = (const int*)  d_in[0];
    const float* emb    = (const float*)d_in[1];
    const float* pos    = (const float*)d_in[2];
    const float* ln1_s  = (const float*)d_in[3];
    const float* ln1_b  = (const float*)d_in[4];
    const float* Pi     = (const float*)d_in[5];
    const float* Po     = (const float*)d_in[6];
    const float* ln2_s  = (const float*)d_in[7];
    const float* ln2_b  = (const float*)d_in[8];
    const float* W1     = (const float*)d_in[9];
    const float* b1     = (const float*)d_in[10];
    const float* W2     = (const float*)d_in[11];
    const float* b2     = (const float*)d_in[12];
    const float* lnf_s  = (const float*)d_in[13];
    const float* lnf_b  = (const float*)d_in[14];
    const float* Wh     = (const float*)d_in[15];
    const float* bh     = (const float*)d_in[16];
    float* out = (float*)d_out;
    const int V = in_sizes[16];

    float *x, *qkv;
    __nv_bfloat16 *yh, *yl, *ah, *al, *hh, *hl;
    __nv_bfloat16 *PiTh, *PiTl, *PoTh, *PoTl, *W1Th, *W1Tl, *W2Th, *W2Tl, *WhTh, *WhTl;
    cudaGetSymbolAddress((void**)&x,    g_x);
    cudaGetSymbolAddress((void**)&qkv,  g_qkv);
    cudaGetSymbolAddress((void**)&yh,   g_yh);   cudaGetSymbolAddress((void**)&yl,   g_yl);
    cudaGetSymbolAddress((void**)&ah,   g_ah);   cudaGetSymbolAddress((void**)&al,   g_al);
    cudaGetSymbolAddress((void**)&hh,   g_hh);   cudaGetSymbolAddress((void**)&hl,   g_hl);
    cudaGetSymbolAddress((void**)&PiTh, g_PiTh); cudaGetSymbolAddress((void**)&PiTl, g_PiTl);
    cudaGetSymbolAddress((void**)&PoTh, g_PoTh); cudaGetSymbolAddress((void**)&PoTl, g_PoTl);
    cudaGetSymbolAddress((void**)&W1Th, g_W1Th); cudaGetSymbolAddress((void**)&W1Tl, g_W1Tl);
    cudaGetSymbolAddress((void**)&W2Th, g_W2Th); cudaGetSymbolAddress((void**)&W2Tl, g_W2Tl);
    cudaGetSymbolAddress((void**)&WhTh, g_WhTh); cudaGetSymbolAddress((void**)&WhTl, g_WhTl);

    cudaFuncSetAttribute(gemm_hmma<false, false, false, true,  false>,
                         cudaFuncAttributeMaxDynamicSharedMemorySize, SMEM_GEMM);
    cudaFuncSetAttribute(gemm_hmma<false, true,  false, true,  false>,
                         cudaFuncAttributeMaxDynamicSharedMemorySize, SMEM_GEMM);
    cudaFuncSetAttribute(gemm_hmma<true,  false, true,  false, true>,
                         cudaFuncAttributeMaxDynamicSharedMemorySize, SMEM_GEMM);
    cudaFuncSetAttribute(gemm_hmma<true,  true,  false, true,  false>,
                         cudaFuncAttributeMaxDynamicSharedMemorySize, SMEM_GEMM);
    cudaFuncSetAttribute(gemm_hmma<true,  false, false, true,  false>,
                         cudaFuncAttributeMaxDynamicSharedMemorySize, SMEM_GEMM);

    dim3 cblk(32, 8);
    // weight conversion (transpose + split)
    for (int l = 0; l < Ll; l++) {
        convT_kernel<<<dim3(96, 32), cblk>>>(Pi + (size_t)l * Dm * 3 * Dm,
                                             PiTh + (size_t)l * 3 * Dm * Dm,
                                             PiTl + (size_t)l * 3 * Dm * Dm, Dm, 3 * Dm);
        convT_kernel<<<dim3(32, 32), cblk>>>(Po + (size_t)l * Dm * Dm,
                                             PoTh + (size_t)l * Dm * Dm,
                                             PoTl + (size_t)l * Dm * Dm, Dm, Dm);
        convT_kernel<<<dim3(128, 32), cblk>>>(W1 + (size_t)l * Dm * 4 * Dm,
                                              W1Th + (size_t)l * 4 * Dm * Dm,
                                              W1Tl + (size_t)l * 4 * Dm * Dm, Dm, 4 * Dm);
        convT_kernel<<<dim3(32, 128), cblk>>>(W2 + (size_t)l * 4 * Dm * Dm,
                                              W2Th + (size_t)l * 4 * Dm * Dm,
                                              W2Tl + (size_t)l * 4 * Dm * Dm, 4 * Dm, Dm);
    }
    convT_kernel<<<dim3(VPAD / 32, 32), cblk>>>(Wh, WhTh, WhTl, Dm, V);

    embed_kernel<<<NTOK, 256>>>(tokens, emb, pos, x);

    for (int l = 0; l < Ll; l++) {
        ln_kernel<<<NTOK, 256>>>(x, yh, yl, ln1_s + l * Dm, ln1_b + l * Dm);
        gemm_hmma<false, false, false, true, false><<<dim3(16, 24), 256, SMEM_GEMM>>>(
            yh, yl, PiTh + (size_t)l * 3 * Dm * Dm, PiTl + (size_t)l * 3 * Dm * Dm,
            nullptr, nullptr, qkv, nullptr, nullptr, 3 * Dm, Dm);
        attn_kernel<<<dim3(8, Hh, Bn), 128>>>(qkv, ah, al);
        gemm_hmma<false, true, false, true, false><<<dim3(16, 8), 256, SMEM_GEMM>>>(
            ah, al, PoTh + (size_t)l * Dm * Dm, PoTl + (size_t)l * Dm * Dm,
            nullptr, x, x, nullptr, nullptr, Dm, Dm);
        ln_kernel<<<NTOK, 256>>>(x, yh, yl, ln2_s + l * Dm, ln2_b + l * Dm);
        gemm_hmma<true, false, true, false, true><<<dim3(16, 32), 256, SMEM_GEMM>>>(
            yh, yl, W1Th + (size_t)l * 4 * Dm * Dm, W1Tl + (size_t)l * 4 * Dm * Dm,
            b1 + (size_t)l * 4 * Dm, nullptr, nullptr, hh, hl, 4 * Dm, Dm);
        gemm_hmma<true, true, false, true, false><<<dim3(16, 8), 256, SMEM_GEMM>>>(
            hh, hl, W2Th + (size_t)l * 4 * Dm * Dm, W2Tl + (size_t)l * 4 * Dm * Dm,
            b2 + (size_t)l * Dm, x, x, nullptr, nullptr, Dm, 4 * Dm);
    }

    ln_kernel<<<NTOK, 256>>>(x, yh, yl, lnf_s, lnf_b);
    gemm_hmma<true, false, false, true, false><<<dim3(16, VPAD / 128), 256, SMEM_GEMM>>>(
        yh, yl, WhTh, WhTl, bh, nullptr, out, nullptr, nullptr, V, Dm);
}

// round 5
// speedup vs baseline: 2.9707x; 1.1889x over previous
#include <cuda_runtime.h>
#include <cuda_bf16.h>
#include <cstdint>
#include <cstddef>

// ---------------------------------------------------------------------------
// GPT-2 forward on GB300 (sm_103 base target): split-bf16 HMMA GEMMs +
// split-bf16 HMMA flash attention.
// B=2, M=1024, D=1024, H=16, K=64, L=4, V=50257.
// ---------------------------------------------------------------------------

#define Bn 2
#define Mseq 1024
#define Dm 1024
#define Hh 16
#define Ll 4
#define NTOK 2048
#define VPAD 50304            // 50257 padded to multiple of 128

// ------------------------------- scratch ----------------------------------
__device__ float g_x[NTOK * Dm];                      // residual (fp32)
__device__ __nv_bfloat16 g_qkvh[NTOK * 3 * Dm], g_qkvl[NTOK * 3 * Dm];
__device__ __nv_bfloat16 g_yh[NTOK * Dm], g_yl[NTOK * Dm];        // LN out split
__device__ __nv_bfloat16 g_ah[NTOK * Dm], g_al[NTOK * Dm];        // attn out split
__device__ __nv_bfloat16 g_hh[NTOK * 4 * Dm], g_hl[NTOK * 4 * Dm];// MLP hidden split
// transposed+split weights: [N][K] K-major
__device__ __nv_bfloat16 g_PiTh[Ll * 3 * Dm * Dm], g_PiTl[Ll * 3 * Dm * Dm];
__device__ __nv_bfloat16 g_PoTh[Ll * Dm * Dm],     g_PoTl[Ll * Dm * Dm];
__device__ __nv_bfloat16 g_W1Th[Ll * 4 * Dm * Dm], g_W1Tl[Ll * 4 * Dm * Dm];
__device__ __nv_bfloat16 g_W2Th[Ll * 4 * Dm * Dm], g_W2Tl[Ll * 4 * Dm * Dm];
__device__ __nv_bfloat16 g_WhTh[(size_t)VPAD * Dm], g_WhTl[(size_t)VPAD * Dm];

// ----------------------------- PTX helpers --------------------------------
__device__ __forceinline__ void ldsm4(uint32_t& r0, uint32_t& r1,
                                      uint32_t& r2, uint32_t& r3, uint32_t addr)
{
    asm volatile("ldmatrix.sync.aligned.m8n8.x4.shared.b16 {%0,%1,%2,%3}, [%4];"
                 : "=r"(r0), "=r"(r1), "=r"(r2), "=r"(r3) : "r"(addr));
}
__device__ __forceinline__ void ldsm4t(uint32_t& r0, uint32_t& r1,
                                       uint32_t& r2, uint32_t& r3, uint32_t addr)
{
    asm volatile("ldmatrix.sync.aligned.m8n8.x4.trans.shared.b16 {%0,%1,%2,%3}, [%4];"
                 : "=r"(r0), "=r"(r1), "=r"(r2), "=r"(r3) : "r"(addr));
}
__device__ __forceinline__ void mma16816(float* d, const uint32_t* a,
                                         uint32_t b0, uint32_t b1)
{
    asm volatile("mma.sync.aligned.m16n8k16.row.col.f32.bf16.bf16.f32 "
                 "{%0,%1,%2,%3}, {%4,%5,%6,%7}, {%8,%9}, {%0,%1,%2,%3};"
                 : "+f"(d[0]), "+f"(d[1]), "+f"(d[2]), "+f"(d[3])
                 : "r"(a[0]), "r"(a[1]), "r"(a[2]), "r"(a[3]), "r"(b0), "r"(b1));
}
__device__ __forceinline__ void cp16(uint32_t sdst, const void* gsrc)
{
    asm volatile("cp.async.cg.shared.global [%0], [%1], 16;"
                 :: "r"(sdst), "l"(gsrc));
}
__device__ __forceinline__ void cp_commit() {
    asm volatile("cp.async.commit_group;");
}
// split a pair of floats into hi/lo bf16x2 registers
__device__ __forceinline__ void split2(float a, float b, uint32_t& hi, uint32_t& lo)
{
    __nv_bfloat162 h = __floats2bfloat162_rn(a, b);
    float ra = a - __bfloat162float(__low2bfloat16(h));
    float rb = b - __bfloat162float(__high2bfloat16(h));
    __nv_bfloat162 l = __floats2bfloat162_rn(ra, rb);
    hi = *(uint32_t*)&h;
    lo = *(uint32_t*)&l;
}

// ---------------------------------------------------------------------------
// Embedding
// ---------------------------------------------------------------------------
__global__ void embed_kernel(const int* __restrict__ tokens,
                             const float* __restrict__ emb,
                             const float* __restrict__ pos,
                             float* __restrict__ x)
{
    int idx = blockIdx.x * blockDim.x + threadIdx.x;
    int row = idx >> 8;
    int d4  = idx & 255;
    int m   = row & (Mseq - 1);
    int t   = tokens[row];
    float4 e = ((const float4*)emb)[(size_t)t * 256 + d4];
    float4 p = ((const float4*)pos)[(size_t)m * 256 + d4];
    float4 o;
    o.x = e.x + p.x; o.y = e.y + p.y; o.z = e.z + p.z; o.w = e.w + p.w;
    ((float4*)x)[idx] = o;
}

// ---------------------------------------------------------------------------
// Transpose + split: W[K,N] fp32 -> Th/Tl [Nrows][K] bf16 (rows >= N zeroed)
// ---------------------------------------------------------------------------
__global__ void convT_kernel(const float* __restrict__ W,
                             __nv_bfloat16* __restrict__ Th,
                             __nv_bfloat16* __restrict__ Tl,
                             int K, int N)
{
    __shared__ float t[32][33];
    int n0 = blockIdx.x * 32, k0 = blockIdx.y * 32;
    int tx = threadIdx.x, ty = threadIdx.y;
    #pragma unroll
    for (int i = 0; i < 32; i += 8) {
        int k = k0 + ty + i, n = n0 + tx;
        t[ty + i][tx] = (n < N) ? W[(size_t)k * N + n] : 0.f;
    }
    __syncthreads();
    #pragma unroll
    for (int i = 0; i < 32; i += 8) {
        int n = n0 + ty + i, k = k0 + tx;
        float v = t[tx][ty + i];
        __nv_bfloat16 h = __float2bfloat16(v);
        Th[(size_t)n * K + k] = h;
        Tl[(size_t)n * K + k] = __float2bfloat16(v - __bfloat162float(h));
    }
}

// ---------------------------------------------------------------------------
// LayerNorm -> split bf16
// ---------------------------------------------------------------------------
__device__ __forceinline__ float blockReduceSum(float val)
{
    __shared__ float sh[8];
    __shared__ float tot;
    int lane = threadIdx.x & 31, wid = threadIdx.x >> 5;
    #pragma unroll
    for (int o = 16; o; o >>= 1) val += __shfl_down_sync(0xffffffffu, val, o);
    if (!lane) sh[wid] = val;
    __syncthreads();
    if (threadIdx.x < 32) {
        float v = (threadIdx.x < 8) ? sh[threadIdx.x] : 0.f;
        #pragma unroll
        for (int o = 4; o; o >>= 1) v += __shfl_down_sync(0xffffffffu, v, o);
        if (!threadIdx.x) tot = v;
    }
    __syncthreads();
    return tot;
}

__global__ void ln_kernel(const float* __restrict__ x,
                          __nv_bfloat16* __restrict__ yh, __nv_bfloat16* __restrict__ yl,
                          const float* __restrict__ s, const float* __restrict__ b)
{
    int row = blockIdx.x, tid = threadIdx.x;
    const float* xr = x + (size_t)row * Dm;
    float v[4];
    #pragma unroll
    for (int i = 0; i < 4; i++) v[i] = xr[tid + 256 * i];
    float mu = blockReduceSum(v[0] + v[1] + v[2] + v[3]) * (1.f / Dm);
    float sq = 0.f;
    #pragma unroll
    for (int i = 0; i < 4; i++) { float d = v[i] - mu; sq += d * d; }
    float var = blockReduceSum(sq) * (1.f / Dm);
    float rs = rsqrtf(var + 1e-5f);
    #pragma unroll
    for (int i = 0; i < 4; i++) {
        int c = tid + 256 * i;
        float val = (v[i] - mu) * rs * s[c] + b[c];
        __nv_bfloat16 h = __float2bfloat16(val);
        yh[(size_t)row * Dm + c] = h;
        yl[(size_t)row * Dm + c] = __float2bfloat16(val - __bfloat162float(h));
    }
}

__device__ __forceinline__ float gelu_new(float v)
{
    float u = 0.7978845608028654f * (v + 0.044715f * v * v * v);
    return 0.5f * v * (1.f + tanhf(u));
}

// ---------------------------------------------------------------------------
// Split-bf16 HMMA GEMM: C[M,N] = (Ah+Al)[M,K] @ (Bh+Bl)[N,K]^T
// ---------------------------------------------------------------------------
#define LDB 80
#define MATB (128 * LDB)
#define STG  (4 * MATB)
#define SMEM_GEMM (2 * STG)

template <bool BIAS, bool RES, bool GELU, bool OUTF32, bool SPLIT>
__global__ __launch_bounds__(256) void gemm_hmma(
    const __nv_bfloat16* __restrict__ Ah, const __nv_bfloat16* __restrict__ Al,
    const __nv_bfloat16* __restrict__ Bh, const __nv_bfloat16* __restrict__ Bl,
    const float* __restrict__ bias, const float* __restrict__ Res,
    float* __restrict__ C, __nv_bfloat16* __restrict__ Ch,
    __nv_bfloat16* __restrict__ Cl, int N, int K)
{
    extern __shared__ char smem[];
    const uint32_t sb = (uint32_t)__cvta_generic_to_shared(smem);
    const int tid  = threadIdx.x;
    const int lane = tid & 31;
    const int wid  = tid >> 5;
    const int bm = blockIdx.x * 128;
    const int bn = blockIdx.y * 128;
    const int wm = (wid & 1) * 64;
    const int wn = (wid >> 1) * 32;

    float acc[4][4][4];
    #pragma unroll
    for (int i = 0; i < 4; i++)
        #pragma unroll
        for (int j = 0; j < 4; j++)
            #pragma unroll
            for (int k = 0; k < 4; k++) acc[i][j][k] = 0.f;

    auto load_stage = [&](int c, int s) {
        const int kc = c * 32;
        const uint32_t st = sb + s * STG;
        #pragma unroll
        for (int i = 0; i < 2; i++) {
            int idx = tid + i * 256;
            int r = idx >> 2, q = idx & 3;
            uint32_t so = st + r * LDB + q * 16;
            size_t ga = (size_t)(bm + r) * K + kc + q * 8;
            cp16(so,            Ah + ga);
            cp16(so + MATB,     Al + ga);
            size_t gb = (size_t)(bn + r) * K + kc + q * 8;
            cp16(so + 2 * MATB, Bh + gb);
            cp16(so + 3 * MATB, Bl + gb);
        }
        cp_commit();
    };

    const int nk = K / 32;
    load_stage(0, 0);

    const int lr  = lane & 15;
    const int kc2 = (lane >> 4) << 3;

    for (int c = 0; c < nk; c++) {
        const int s = c & 1;
        if (c + 1 < nk) {
            load_stage(c + 1, s ^ 1);
            asm volatile("cp.async.wait_group 1;");
        } else {
            asm volatile("cp.async.wait_group 0;");
        }
        __syncthreads();

        const uint32_t st = sb + s * STG;
        #pragma unroll
        for (int ks = 0; ks < 2; ks++) {
            const uint32_t ao = st + (wm + lr) * LDB + (ks * 16 + kc2) * 2;
            const uint32_t bo = st + 2 * MATB + (wn + lr) * LDB + (ks * 16 + kc2) * 2;
            uint32_t ah[4][4], al[4][4], bh[2][4], bl[2][4];
            #pragma unroll
            for (int mt = 0; mt < 4; mt++)
                ldsm4(ah[mt][0], ah[mt][1], ah[mt][2], ah[mt][3], ao + mt * 16 * LDB);
            #pragma unroll
            for (int mt = 0; mt < 4; mt++)
                ldsm4(al[mt][0], al[mt][1], al[mt][2], al[mt][3],
                      ao + MATB + mt * 16 * LDB);
            #pragma unroll
            for (int g = 0; g < 2; g++)
                ldsm4(bh[g][0], bh[g][1], bh[g][2], bh[g][3], bo + g * 16 * LDB);
            #pragma unroll
            for (int g = 0; g < 2; g++)
                ldsm4(bl[g][0], bl[g][1], bl[g][2], bl[g][3],
                      bo + MATB + g * 16 * LDB);

            #pragma unroll
            for (int mt = 0; mt < 4; mt++)
                #pragma unroll
                for (int nt = 0; nt < 4; nt++) {
                    int g = nt >> 1, h = nt & 1;
                    mma16816(acc[mt][nt], ah[mt], bh[g][h], bh[g][2 + h]);
                    mma16816(acc[mt][nt], ah[mt], bl[g][h], bl[g][2 + h]);
                    mma16816(acc[mt][nt], al[mt], bh[g][h], bh[g][2 + h]);
                }
        }
        __syncthreads();
    }

    const bool headN = (N & 1) != 0;
    #pragma unroll
    for (int mt = 0; mt < 4; mt++) {
        #pragma unroll
        for (int nt = 0; nt < 4; nt++) {
            int row0 = bm + wm + mt * 16 + (lane >> 2);
            int col  = bn + wn + nt * 8 + (lane & 3) * 2;
            #pragma unroll
            for (int half = 0; half < 2; half++) {
                int row = row0 + half * 8;
                float v0 = acc[mt][nt][half * 2];
                float v1 = acc[mt][nt][half * 2 + 1];
                if (!headN) {
                    size_t base = (size_t)row * N + col;
                    if (BIAS) { v0 += bias[col]; v1 += bias[col + 1]; }
                    if (GELU) { v0 = gelu_new(v0); v1 = gelu_new(v1); }
                    if (RES) {
                        float2 r = *(const float2*)&Res[base];
                        v0 += r.x; v1 += r.y;
                    }
                    if (OUTF32) {
                        float2 o; o.x = v0; o.y = v1;
                        *(float2*)&C[base] = o;
                    }
                    if (SPLIT) {
                        uint32_t hp, lp;
                        split2(v0, v1, hp, lp);
                        *(uint32_t*)&Ch[base] = hp;
                        *(uint32_t*)&Cl[base] = lp;
                    }
                } else {
                    size_t rb = (size_t)row * N;
                    if (col < N) {
                        float v = v0;
                        if (BIAS) v += bias[col];
                        C[rb + col] = v;
                    }
                    if (col + 1 < N) {
                        float v = v1;
                        if (BIAS) v += bias[col + 1];
                        C[rb + col + 1] = v;
                    }
                }
            }
        }
    }
}

// ---------------------------------------------------------------------------
// Tensorized flash attention (causal), split-bf16 in/out, fp32 softmax.
// CTA = 128 queries x one (b,h); 8 warps x 16 queries.
// smem: Qh/Ql[128][72], Kh/Kl/Vh/Vl[64][72], pitch 144B (conflict-free ldsm).
// ---------------------------------------------------------------------------
#define AROWB 144
#define SMEM_ATT 73728

__global__ __launch_bounds__(256) void attn_tc(
    const __nv_bfloat16* __restrict__ qkvh,
    const __nv_bfloat16* __restrict__ qkvl,
    __nv_bfloat16* __restrict__ ah, __nv_bfloat16* __restrict__ al)
{
    extern __shared__ char smem[];
    const uint32_t sb  = (uint32_t)__cvta_generic_to_shared(smem);
    const uint32_t sQh = sb,          sQl = sb + 18432;
    const uint32_t sKh = sb + 36864,  sKl = sb + 46080;
    const uint32_t sVh = sb + 55296,  sVl = sb + 64512;
    const int tid = threadIdx.x, lane = tid & 31, w = tid >> 5;
    const int qt = gridDim.x - 1 - blockIdx.x;     // big tiles first
    const int h = blockIdx.y, b = blockIdx.z;

    // ---- load Q tile (split bf16, 16B chunks) ----
    #pragma unroll
    for (int i = 0; i < 4; i++) {
        int idx = tid + i * 256;            // 0..1023
        int r = idx >> 3, q8 = idx & 7;
        size_t g = ((size_t)(b * Mseq + qt * 128 + r)) * 3072 + h * 192 + q8 * 8;
        cp16(sQh + r * AROWB + q8 * 16, qkvh + g);
        cp16(sQl + r * AROWB + q8 * 16, qkvl + g);
    }
    cp_commit();
    asm volatile("cp.async.wait_group 0;");
    __syncthreads();

    const int lr  = lane & 15;
    const int khi = (lane >> 4) << 3;

    uint32_t qfh[4][4], qfl[4][4];
    #pragma unroll
    for (int kc = 0; kc < 4; kc++) {
        uint32_t ad = (w * 16 + lr) * AROWB + (kc * 16 + khi) * 2;
        ldsm4(qfh[kc][0], qfh[kc][1], qfh[kc][2], qfh[kc][3], sQh + ad);
        ldsm4(qfl[kc][0], qfl[kc][1], qfl[kc][2], qfl[kc][3], sQl + ad);
    }

    float oacc[8][4];
    #pragma unroll
    for (int i = 0; i < 8; i++)
        #pragma unroll
        for (int j = 0; j < 4; j++) oacc[i][j] = 0.f;
    float mA = -1e30f, mB = -1e30f, lA = 0.f, lB = 0.f;

    const int q0   = qt * 128 + w * 16;
    const int rowA = q0 + (lane >> 2);
    const int rowB = rowA + 8;

    const int nkt = 2 * qt + 2;
    for (int kt = 0; kt < nkt; kt++) {
        // ---- load K/V tile ----
        #pragma unroll
        for (int i = 0; i < 2; i++) {
            int idx = tid + i * 256;        // 0..511
            int r = idx >> 3, q8 = idx & 7;
            size_t base = ((size_t)(b * Mseq + kt * 64 + r)) * 3072 + h * 192;
            uint32_t sd = r * AROWB + q8 * 16;
            cp16(sKh + sd, qkvh + base + 64  + q8 * 8);
            cp16(sKl + sd, qkvl + base + 64  + q8 * 8);
            cp16(sVh + sd, qkvh + base + 128 + q8 * 8);
            cp16(sVl + sd, qkvl + base + 128 + q8 * 8);
        }
        cp_commit();
        asm volatile("cp.async.wait_group 0;");
        __syncthreads();

        if (kt * 64 <= q0 + 15) {
            // ---- S = Q K^T (3-pass split bf16) ----
            float sacc[8][4];
            #pragma unroll
            for (int i = 0; i < 8; i++)
                #pragma unroll
                for (int j = 0; j < 4; j++) sacc[i][j] = 0.f;

            #pragma unroll
            for (int kc = 0; kc < 4; kc++) {
                uint32_t kfh[4][4], kfl[4][4];
                #pragma unroll
                for (int g = 0; g < 4; g++) {
                    uint32_t ad = (g * 16 + lr) * AROWB + (kc * 16 + khi) * 2;
                    ldsm4(kfh[g][0], kfh[g][1], kfh[g][2], kfh[g][3], sKh + ad);
                    ldsm4(kfl[g][0], kfl[g][1], kfl[g][2], kfl[g][3], sKl + ad);
                }
                #pragma unroll
                for (int nt = 0; nt < 8; nt++) {
                    int g = nt >> 1, hh = nt & 1;
                    mma16816(sacc[nt], qfh[kc], kfh[g][hh], kfh[g][2 + hh]);
                    mma16816(sacc[nt], qfh[kc], kfl[g][hh], kfl[g][2 + hh]);
                    mma16816(sacc[nt], qfl[kc], kfh[g][hh], kfh[g][2 + hh]);
                }
            }

            // ---- scale, causal mask, online softmax ----
            float mxA = -1e30f, mxB = -1e30f;
            #pragma unroll
            for (int nt = 0; nt < 8; nt++) {
                int k0 = kt * 64 + nt * 8 + (lane & 3) * 2;
                float s0 = sacc[nt][0] * 0.125f;
                float s1 = sacc[nt][1] * 0.125f;
                float s2 = sacc[nt][2] * 0.125f;
                float s3 = sacc[nt][3] * 0.125f;
                if (k0     > rowA) s0 = -1e30f;
                if (k0 + 1 > rowA) s1 = -1e30f;
                if (k0     > rowB) s2 = -1e30f;
                if (k0 + 1 > rowB) s3 = -1e30f;
                sacc[nt][0] = s0; sacc[nt][1] = s1;
                sacc[nt][2] = s2; sacc[nt][3] = s3;
                mxA = fmaxf(mxA, fmaxf(s0, s1));
                mxB = fmaxf(mxB, fmaxf(s2, s3));
            }
            mxA = fmaxf(mxA, __shfl_xor_sync(0xffffffffu, mxA, 1));
            mxA = fmaxf(mxA, __shfl_xor_sync(0xffffffffu, mxA, 2));
            mxB = fmaxf(mxB, __shfl_xor_sync(0xffffffffu, mxB, 1));
            mxB = fmaxf(mxB, __shfl_xor_sync(0xffffffffu, mxB, 2));
            float mnA = fmaxf(mA, mxA), mnB = fmaxf(mB, mxB);
            float cA = __expf(mA - mnA), cB = __expf(mB - mnB);
            mA = mnA; mB = mnB;

            float sA = 0.f, sB = 0.f;
            #pragma unroll
            for (int nt = 0; nt < 8; nt++) {
                sacc[nt][0] = __expf(sacc[nt][0] - mnA);
                sacc[nt][1] = __expf(sacc[nt][1] - mnA);
                sacc[nt][2] = __expf(sacc[nt][2] - mnB);
                sacc[nt][3] = __expf(sacc[nt][3] - mnB);
                sA += sacc[nt][0] + sacc[nt][1];
                sB += sacc[nt][2] + sacc[nt][3];
            }
            sA += __shfl_xor_sync(0xffffffffu, sA, 1);
            sA += __shfl_xor_sync(0xffffffffu, sA, 2);
            sB += __shfl_xor_sync(0xffffffffu, sB, 1);
            sB += __shfl_xor_sync(0xffffffffu, sB, 2);
            lA = lA * cA + sA;
            lB = lB * cB + sB;
            #pragma unroll
            for (int nt = 0; nt < 8; nt++) {
                oacc[nt][0] *= cA; oacc[nt][1] *= cA;
                oacc[nt][2] *= cB; oacc[nt][3] *= cB;
            }

            // ---- O += P V (3-pass split bf16), V via ldmatrix.trans ----
            #pragma unroll
            for (int kc = 0; kc < 4; kc++) {
                uint32_t pah[4], pal[4];
                split2(sacc[2 * kc][0],     sacc[2 * kc][1],     pah[0], pal[0]);
                split2(sacc[2 * kc][2],     sacc[2 * kc][3],     pah[1], pal[1]);
                split2(sacc[2 * kc + 1][0], sacc[2 * kc + 1][1], pah[2], pal[2]);
                split2(sacc[2 * kc + 1][2], sacc[2 * kc + 1][3], pah[3], pal[3]);

                uint32_t vfh[4][4], vfl[4][4];
                #pragma unroll
                for (int dg = 0; dg < 4; dg++) {
                    uint32_t ad = (kc * 16 + (lane & 7) + ((lane >> 4) << 3)) * AROWB
                                + (dg * 16 + ((lane >> 3) & 1) * 8) * 2;
                    ldsm4t(vfh[dg][0], vfh[dg][1], vfh[dg][2], vfh[dg][3], sVh + ad);
                    ldsm4t(vfl[dg][0], vfl[dg][1], vfl[dg][2], vfl[dg][3], sVl + ad);
                }
                #pragma unroll
                for (int nt = 0; nt < 8; nt++) {
                    int dg = nt >> 1, hh = nt & 1;
                    mma16816(oacc[nt], pah, vfh[dg][hh], vfh[dg][hh + 2]);
                    mma16816(oacc[nt], pah, vfl[dg][hh], vfl[dg][hh + 2]);
                    mma16816(oacc[nt], pal, vfh[dg][hh], vfh[dg][hh + 2]);
                }
            }
        }
        __syncthreads();
    }

    // ---- normalize + split-store ----
    float iA = 1.f / lA, iB = 1.f / lB;
    #pragma unroll
    for (int nt = 0; nt < 8; nt++) {
        int col = h * 64 + nt * 8 + (lane & 3) * 2;
        size_t gA = ((size_t)(b * Mseq + rowA)) * Dm + col;
        size_t gB = ((size_t)(b * Mseq + rowB)) * Dm + col;
        uint32_t hp, lp;
        split2(oacc[nt][0] * iA, oacc[nt][1] * iA, hp, lp);
        *(uint32_t*)&ah[gA] = hp;
        *(uint32_t*)&al[gA] = lp;
        split2(oacc[nt][2] * iB, oacc[nt][3] * iB, hp, lp);
        *(uint32_t*)&ah[gB] = hp;
        *(uint32_t*)&al[gB] = lp;
    }
}

// ---------------------------------------------------------------------------
// Host launcher
// ---------------------------------------------------------------------------
extern "C" void kernel_launch(void* const* d_in, const int* in_sizes, int n_in,
                              void* d_out, int out_size)
{
    const int*   tokens = (const int*)  d_in[0];
    const float* emb    = (const float*)d_in[1];
    const float* pos    = (const float*)d_in[2];
    const float* ln1_s  = (const float*)d_in[3];
    const float* ln1_b  = (const float*)d_in[4];
    const float* Pi     = (const float*)d_in[5];
    const float* Po     = (const float*)d_in[6];
    const float* ln2_s  = (const float*)d_in[7];
    const float* ln2_b  = (const float*)d_in[8];
    const float* W1     = (const float*)d_in[9];
    const float* b1     = (const float*)d_in[10];
    const float* W2     = (const float*)d_in[11];
    const float* b2     = (const float*)d_in[12];
    const float* lnf_s  = (const float*)d_in[13];
    const float* lnf_b  = (const float*)d_in[14];
    const float* Wh     = (const float*)d_in[15];
    const float* bh     = (const float*)d_in[16];
    float* out = (float*)d_out;
    const int V = in_sizes[16];

    float *x;
    __nv_bfloat16 *qkvh, *qkvl, *yh, *yl, *ah, *al, *hh, *hl;
    __nv_bfloat16 *PiTh, *PiTl, *PoTh, *PoTl, *W1Th, *W1Tl, *W2Th, *W2Tl, *WhTh, *WhTl;
    cudaGetSymbolAddress((void**)&x,    g_x);
    cudaGetSymbolAddress((void**)&qkvh, g_qkvh); cudaGetSymbolAddress((void**)&qkvl, g_qkvl);
    cudaGetSymbolAddress((void**)&yh,   g_yh);   cudaGetSymbolAddress((void**)&yl,   g_yl);
    cudaGetSymbolAddress((void**)&ah,   g_ah);   cudaGetSymbolAddress((void**)&al,   g_al);
    cudaGetSymbolAddress((void**)&hh,   g_hh);   cudaGetSymbolAddress((void**)&hl,   g_hl);
    cudaGetSymbolAddress((void**)&PiTh, g_PiTh); cudaGetSymbolAddress((void**)&PiTl, g_PiTl);
    cudaGetSymbolAddress((void**)&PoTh, g_PoTh); cudaGetSymbolAddress((void**)&PoTl, g_PoTl);
    cudaGetSymbolAddress((void**)&W1Th, g_W1Th); cudaGetSymbolAddress((void**)&W1Tl, g_W1Tl);
    cudaGetSymbolAddress((void**)&W2Th, g_W2Th); cudaGetSymbolAddress((void**)&W2Tl, g_W2Tl);
    cudaGetSymbolAddress((void**)&WhTh, g_WhTh); cudaGetSymbolAddress((void**)&WhTl, g_WhTl);

    cudaFuncSetAttribute(gemm_hmma<false, false, false, false, true>,
                         cudaFuncAttributeMaxDynamicSharedMemorySize, SMEM_GEMM);
    cudaFuncSetAttribute(gemm_hmma<false, true,  false, true,  false>,
                         cudaFuncAttributeMaxDynamicSharedMemorySize, SMEM_GEMM);
    cudaFuncSetAttribute(gemm_hmma<true,  false, true,  false, true>,
                         cudaFuncAttributeMaxDynamicSharedMemorySize, SMEM_GEMM);
    cudaFuncSetAttribute(gemm_hmma<true,  true,  false, true,  false>,
                         cudaFuncAttributeMaxDynamicSharedMemorySize, SMEM_GEMM);
    cudaFuncSetAttribute(gemm_hmma<true,  false, false, true,  false>,
                         cudaFuncAttributeMaxDynamicSharedMemorySize, SMEM_GEMM);
    cudaFuncSetAttribute(attn_tc,
                         cudaFuncAttributeMaxDynamicSharedMemorySize, SMEM_ATT);

    dim3 cblk(32, 8);
    for (int l = 0; l < Ll; l++) {
        convT_kernel<<<dim3(96, 32), cblk>>>(Pi + (size_t)l * Dm * 3 * Dm,
                                             PiTh + (size_t)l * 3 * Dm * Dm,
                                             PiTl + (size_t)l * 3 * Dm * Dm, Dm, 3 * Dm);
        convT_kernel<<<dim3(32, 32), cblk>>>(Po + (size_t)l * Dm * Dm,
                                             PoTh + (size_t)l * Dm * Dm,
                                             PoTl + (size_t)l * Dm * Dm, Dm, Dm);
        convT_kernel<<<dim3(128, 32), cblk>>>(W1 + (size_t)l * Dm * 4 * Dm,
                                              W1Th + (size_t)l * 4 * Dm * Dm,
                                              W1Tl + (size_t)l * 4 * Dm * Dm, Dm, 4 * Dm);
        convT_kernel<<<dim3(32, 128), cblk>>>(W2 + (size_t)l * 4 * Dm * Dm,
                                              W2Th + (size_t)l * 4 * Dm * Dm,
                                              W2Tl + (size_t)l * 4 * Dm * Dm, 4 * Dm, Dm);
    }
    convT_kernel<<<dim3(VPAD / 32, 32), cblk>>>(Wh, WhTh, WhTl, Dm, V);

    embed_kernel<<<NTOK, 256>>>(tokens, emb, pos, x);

    for (int l = 0; l < Ll; l++) {
        ln_kernel<<<NTOK, 256>>>(x, yh, yl, ln1_s + l * Dm, ln1_b + l * Dm);
        gemm_hmma<false, false, false, false, true><<<dim3(16, 24), 256, SMEM_GEMM>>>(
            yh, yl, PiTh + (size_t)l * 3 * Dm * Dm, PiTl + (size_t)l * 3 * Dm * Dm,
            nullptr, nullptr, nullptr, qkvh, qkvl, 3 * Dm, Dm);
        attn_tc<<<dim3(8, Hh, Bn), 256, SMEM_ATT>>>(qkvh, qkvl, ah, al);
        gemm_hmma<false, true, false, true, false><<<dim3(16, 8), 256, SMEM_GEMM>>>(
            ah, al, PoTh + (size_t)l * Dm * Dm, PoTl + (size_t)l * Dm * Dm,
            nullptr, x, x, nullptr, nullptr, Dm, Dm);
        ln_kernel<<<NTOK, 256>>>(x, yh, yl, ln2_s + l * Dm, ln2_b + l * Dm);
        gemm_hmma<true, false, true, false, true><<<dim3(16, 32), 256, SMEM_GEMM>>>(
            yh, yl, W1Th + (size_t)l * 4 * Dm * Dm, W1Tl + (size_t)l * 4 * Dm * Dm,
            b1 + (size_t)l * 4 * Dm, nullptr, nullptr, hh, hl, 4 * Dm, Dm);
        gemm_hmma<true, true, false, true, false><<<dim3(16, 8), 256, SMEM_GEMM>>>(
            hh, hl, W2Th + (size_t)l * 4 * Dm * Dm, W2Tl + (size_t)l * 4 * Dm * Dm,
            b2 + (size_t)l * Dm, x, x, nullptr, nullptr, Dm, 4 * Dm);
    }

    ln_kernel<<<NTOK, 256>>>(x, yh, yl, lnf_s, lnf_b);
    gemm_hmma<true, false, false, true, false><<<dim3(16, VPAD / 128), 256, SMEM_GEMM>>>(
        yh, yl, WhTh, WhTl, bh, nullptr, out, nullptr, nullptr, V, Dm);
}

// round 6
// speedup vs baseline: 3.0044x; 1.0113x over previous
#include <cuda_runtime.h>
#include <cuda_bf16.h>
#include <cstdint>
#include <cstddef>

// ---------------------------------------------------------------------------
// GPT-2 forward on GB300 (sm_103 base target): split-bf16 HMMA GEMMs +
// split-bf16 HMMA flash attention.
// B=2, M=1024, D=1024, H=16, K=64, L=4, V=50257.
// ---------------------------------------------------------------------------

#define Bn 2
#define Mseq 1024
#define Dm 1024
#define Hh 16
#define Ll 4
#define NTOK 2048
#define VPAD 50304            // 50257 padded to multiple of 128

// ------------------------------- scratch ----------------------------------
__device__ float g_x[NTOK * Dm];                      // residual (fp32)
__device__ __nv_bfloat16 g_qkvh[NTOK * 3 * Dm], g_qkvl[NTOK * 3 * Dm];
__device__ __nv_bfloat16 g_yh[NTOK * Dm], g_yl[NTOK * Dm];        // LN out split
__device__ __nv_bfloat16 g_ah[NTOK * Dm], g_al[NTOK * Dm];        // attn out split
__device__ __nv_bfloat16 g_hh[NTOK * 4 * Dm], g_hl[NTOK * 4 * Dm];// MLP hidden split
// transposed+split weights: [N][K] K-major
__device__ __nv_bfloat16 g_PiTh[Ll * 3 * Dm * Dm], g_PiTl[Ll * 3 * Dm * Dm];
__device__ __nv_bfloat16 g_PoTh[Ll * Dm * Dm],     g_PoTl[Ll * Dm * Dm];
__device__ __nv_bfloat16 g_W1Th[Ll * 4 * Dm * Dm], g_W1Tl[Ll * 4 * Dm * Dm];
__device__ __nv_bfloat16 g_W2Th[Ll * 4 * Dm * Dm], g_W2Tl[Ll * 4 * Dm * Dm];
__device__ __nv_bfloat16 g_WhTh[(size_t)VPAD * Dm], g_WhTl[(size_t)VPAD * Dm];

// ----------------------------- PTX helpers --------------------------------
__device__ __forceinline__ void ldsm4(uint32_t& r0, uint32_t& r1,
                                      uint32_t& r2, uint32_t& r3, uint32_t addr)
{
    asm volatile("ldmatrix.sync.aligned.m8n8.x4.shared.b16 {%0,%1,%2,%3}, [%4];"
                 : "=r"(r0), "=r"(r1), "=r"(r2), "=r"(r3) : "r"(addr));
}
__device__ __forceinline__ void ldsm4t(uint32_t& r0, uint32_t& r1,
                                       uint32_t& r2, uint32_t& r3, uint32_t addr)
{
    asm volatile("ldmatrix.sync.aligned.m8n8.x4.trans.shared.b16 {%0,%1,%2,%3}, [%4];"
                 : "=r"(r0), "=r"(r1), "=r"(r2), "=r"(r3) : "r"(addr));
}
__device__ __forceinline__ void mma16816(float* d, const uint32_t* a,
                                         uint32_t b0, uint32_t b1)
{
    asm volatile("mma.sync.aligned.m16n8k16.row.col.f32.bf16.bf16.f32 "
                 "{%0,%1,%2,%3}, {%4,%5,%6,%7}, {%8,%9}, {%0,%1,%2,%3};"
                 : "+f"(d[0]), "+f"(d[1]), "+f"(d[2]), "+f"(d[3])
                 : "r"(a[0]), "r"(a[1]), "r"(a[2]), "r"(a[3]), "r"(b0), "r"(b1));
}
__device__ __forceinline__ void cp16(uint32_t sdst, const void* gsrc)
{
    asm volatile("cp.async.cg.shared.global [%0], [%1], 16;"
                 :: "r"(sdst), "l"(gsrc));
}
__device__ __forceinline__ void cp_commit() {
    asm volatile("cp.async.commit_group;");
}
// split a pair of floats into hi/lo bf16x2 registers
__device__ __forceinline__ void split2(float a, float b, uint32_t& hi, uint32_t& lo)
{
    __nv_bfloat162 h = __floats2bfloat162_rn(a, b);
    float ra = a - __bfloat162float(__low2bfloat16(h));
    float rb = b - __bfloat162float(__high2bfloat16(h));
    __nv_bfloat162 l = __floats2bfloat162_rn(ra, rb);
    hi = *(uint32_t*)&h;
    lo = *(uint32_t*)&l;
}

// ---------------------------------------------------------------------------
// Embedding
// ---------------------------------------------------------------------------
__global__ void embed_kernel(const int* __restrict__ tokens,
                             const float* __restrict__ emb,
                             const float* __restrict__ pos,
                             float* __restrict__ x)
{
    int idx = blockIdx.x * blockDim.x + threadIdx.x;
    int row = idx >> 8;
    int d4  = idx & 255;
    int m   = row & (Mseq - 1);
    int t   = tokens[row];
    float4 e = ((const float4*)emb)[(size_t)t * 256 + d4];
    float4 p = ((const float4*)pos)[(size_t)m * 256 + d4];
    float4 o;
    o.x = e.x + p.x; o.y = e.y + p.y; o.z = e.z + p.z; o.w = e.w + p.w;
    ((float4*)x)[idx] = o;
}

// ---------------------------------------------------------------------------
// Transpose + split: W[K,N] fp32 -> Th/Tl [Nrows][K] bf16 (rows >= N zeroed).
// Layered over blockIdx.z (weight stride wstr/tstr); vectorized uint32 stores.
// ---------------------------------------------------------------------------
__global__ void convT_kernel(const float* __restrict__ W,
                             __nv_bfloat16* __restrict__ Th,
                             __nv_bfloat16* __restrict__ Tl,
                             int K, int N, size_t wstr, size_t tstr)
{
    __shared__ float t[32][33];
    W  += (size_t)blockIdx.z * wstr;
    Th += (size_t)blockIdx.z * tstr;
    Tl += (size_t)blockIdx.z * tstr;
    int n0 = blockIdx.x * 32, k0 = blockIdx.y * 32;
    int tx = threadIdx.x, ty = threadIdx.y;
    #pragma unroll
    for (int i = 0; i < 32; i += 8) {
        int k = k0 + ty + i, n = n0 + tx;
        t[ty + i][tx] = (n < N) ? W[(size_t)k * N + n] : 0.f;
    }
    __syncthreads();
    const int tid = ty * 32 + tx;
    #pragma unroll
    for (int i = 0; i < 2; i++) {
        int e  = tid + i * 256;          // 0..511 pair index
        int n  = e >> 4;                 // 0..31
        int kp = e & 15;                 // k pair 0..15
        float v0 = t[2 * kp][n], v1 = t[2 * kp + 1][n];
        __nv_bfloat162 h2 = __floats2bfloat162_rn(v0, v1);
        float r0 = v0 - __bfloat162float(__low2bfloat16(h2));
        float r1 = v1 - __bfloat162float(__high2bfloat16(h2));
        __nv_bfloat162 l2 = __floats2bfloat162_rn(r0, r1);
        size_t o = (size_t)(n0 + n) * K + k0 + 2 * kp;
        *(uint32_t*)&Th[o] = *(uint32_t*)&h2;
        *(uint32_t*)&Tl[o] = *(uint32_t*)&l2;
    }
}

// ---------------------------------------------------------------------------
// LayerNorm -> split bf16
// ---------------------------------------------------------------------------
__device__ __forceinline__ float blockReduceSum(float val)
{
    __shared__ float sh[8];
    __shared__ float tot;
    int lane = threadIdx.x & 31, wid = threadIdx.x >> 5;
    #pragma unroll
    for (int o = 16; o; o >>= 1) val += __shfl_down_sync(0xffffffffu, val, o);
    if (!lane) sh[wid] = val;
    __syncthreads();
    if (threadIdx.x < 32) {
        float v = (threadIdx.x < 8) ? sh[threadIdx.x] : 0.f;
        #pragma unroll
        for (int o = 4; o; o >>= 1) v += __shfl_down_sync(0xffffffffu, v, o);
        if (!threadIdx.x) tot = v;
    }
    __syncthreads();
    return tot;
}

__global__ void ln_kernel(const float* __restrict__ x,
                          __nv_bfloat16* __restrict__ yh, __nv_bfloat16* __restrict__ yl,
                          const float* __restrict__ s, const float* __restrict__ b)
{
    int row = blockIdx.x, tid = threadIdx.x;
    const float* xr = x + (size_t)row * Dm;
    float v[4];
    #pragma unroll
    for (int i = 0; i < 4; i++) v[i] = xr[tid + 256 * i];
    float mu = blockReduceSum(v[0] + v[1] + v[2] + v[3]) * (1.f / Dm);
    float sq = 0.f;
    #pragma unroll
    for (int i = 0; i < 4; i++) { float d = v[i] - mu; sq += d * d; }
    float var = blockReduceSum(sq) * (1.f / Dm);
    float rs = rsqrtf(var + 1e-5f);
    #pragma unroll
    for (int i = 0; i < 4; i++) {
        int c = tid + 256 * i;
        float val = (v[i] - mu) * rs * s[c] + b[c];
        __nv_bfloat16 h = __float2bfloat16(val);
        yh[(size_t)row * Dm + c] = h;
        yl[(size_t)row * Dm + c] = __float2bfloat16(val - __bfloat162float(h));
    }
}

__device__ __forceinline__ float gelu_new(float v)
{
    float u = 0.7978845608028654f * (v + 0.044715f * v * v * v);
    return 0.5f * v * (1.f + tanhf(u));
}

// ---------------------------------------------------------------------------
// Split-bf16 HMMA GEMM: C[M,N] = (Ah+Al)[M,K] @ (Bh+Bl)[N,K]^T
// CTA tile 128x128, BK=32, 128 threads (4 warps, warp tile 64x64),
// 2 CTAs/SM, cp.async double buffer, 3-pass accumulation.
// ---------------------------------------------------------------------------
#define LDB 80
#define MATB (128 * LDB)
#define STG  (4 * MATB)
#define SMEM_GEMM (2 * STG)

template <bool BIAS, bool RES, bool GELU, bool OUTF32, bool SPLIT>
__global__ __launch_bounds__(128, 2) void gemm_hmma(
    const __nv_bfloat16* __restrict__ Ah, const __nv_bfloat16* __restrict__ Al,
    const __nv_bfloat16* __restrict__ Bh, const __nv_bfloat16* __restrict__ Bl,
    const float* __restrict__ bias, const float* __restrict__ Res,
    float* __restrict__ C, __nv_bfloat16* __restrict__ Ch,
    __nv_bfloat16* __restrict__ Cl, int N, int K)
{
    extern __shared__ char smem[];
    const uint32_t sb = (uint32_t)__cvta_generic_to_shared(smem);
    const int tid  = threadIdx.x;
    const int lane = tid & 31;
    const int wid  = tid >> 5;
    const int bm = blockIdx.x * 128;
    const int bn = blockIdx.y * 128;
    const int wm = (wid & 1) * 64;
    const int wn = (wid >> 1) * 64;

    float acc[4][8][4];
    #pragma unroll
    for (int i = 0; i < 4; i++)
        #pragma unroll
        for (int j = 0; j < 8; j++)
            #pragma unroll
            for (int k = 0; k < 4; k++) acc[i][j][k] = 0.f;

    auto load_stage = [&](int c, int s) {
        const int kc = c * 32;
        const uint32_t st = sb + s * STG;
        #pragma unroll
        for (int i = 0; i < 4; i++) {
            int idx = tid + i * 128;          // 0..511
            int r = idx >> 2, q = idx & 3;
            uint32_t so = st + r * LDB + q * 16;
            size_t ga = (size_t)(bm + r) * K + kc + q * 8;
            cp16(so,            Ah + ga);
            cp16(so + MATB,     Al + ga);
            size_t gb = (size_t)(bn + r) * K + kc + q * 8;
            cp16(so + 2 * MATB, Bh + gb);
            cp16(so + 3 * MATB, Bl + gb);
        }
        cp_commit();
    };

    const int nk = K / 32;
    load_stage(0, 0);

    const int lr  = lane & 15;
    const int kc2 = (lane >> 4) << 3;

    for (int c = 0; c < nk; c++) {
        const int s = c & 1;
        if (c + 1 < nk) {
            load_stage(c + 1, s ^ 1);
            asm volatile("cp.async.wait_group 1;");
        } else {
            asm volatile("cp.async.wait_group 0;");
        }
        __syncthreads();

        const uint32_t st = sb + s * STG;
        #pragma unroll
        for (int ks = 0; ks < 2; ks++) {
            const uint32_t ao = st + (wm + lr) * LDB + (ks * 16 + kc2) * 2;
            const uint32_t bo = st + 2 * MATB + (wn + lr) * LDB + (ks * 16 + kc2) * 2;
            uint32_t ah[4][4], al[4][4], bh[4][4], bl[4][4];
            #pragma unroll
            for (int mt = 0; mt < 4; mt++)
                ldsm4(ah[mt][0], ah[mt][1], ah[mt][2], ah[mt][3], ao + mt * 16 * LDB);
            #pragma unroll
            for (int mt = 0; mt < 4; mt++)
                ldsm4(al[mt][0], al[mt][1], al[mt][2], al[mt][3],
                      ao + MATB + mt * 16 * LDB);
            #pragma unroll
            for (int g = 0; g < 4; g++)
                ldsm4(bh[g][0], bh[g][1], bh[g][2], bh[g][3], bo + g * 16 * LDB);
            #pragma unroll
            for (int g = 0; g < 4; g++)
                ldsm4(bl[g][0], bl[g][1], bl[g][2], bl[g][3],
                      bo + MATB + g * 16 * LDB);

            #pragma unroll
            for (int mt = 0; mt < 4; mt++)
                #pragma unroll
                for (int nt = 0; nt < 8; nt++) {
                    int g = nt >> 1, h = nt & 1;
                    mma16816(acc[mt][nt], ah[mt], bh[g][h], bh[g][2 + h]);
                    mma16816(acc[mt][nt], ah[mt], bl[g][h], bl[g][2 + h]);
                    mma16816(acc[mt][nt], al[mt], bh[g][h], bh[g][2 + h]);
                }
        }
        __syncthreads();
    }

    const bool headN = (N & 1) != 0;
    #pragma unroll
    for (int mt = 0; mt < 4; mt++) {
        #pragma unroll
        for (int nt = 0; nt < 8; nt++) {
            int row0 = bm + wm + mt * 16 + (lane >> 2);
            int col  = bn + wn + nt * 8 + (lane & 3) * 2;
            #pragma unroll
            for (int half = 0; half < 2; half++) {
                int row = row0 + half * 8;
                float v0 = acc[mt][nt][half * 2];
                float v1 = acc[mt][nt][half * 2 + 1];
                if (!headN) {
                    size_t base = (size_t)row * N + col;
                    if (BIAS) { v0 += bias[col]; v1 += bias[col + 1]; }
                    if (GELU) { v0 = gelu_new(v0); v1 = gelu_new(v1); }
                    if (RES) {
                        float2 r = *(const float2*)&Res[base];
                        v0 += r.x; v1 += r.y;
                    }
                    if (OUTF32) {
                        float2 o; o.x = v0; o.y = v1;
                        *(float2*)&C[base] = o;
                    }
                    if (SPLIT) {
                        uint32_t hp, lp;
                        split2(v0, v1, hp, lp);
                        *(uint32_t*)&Ch[base] = hp;
                        *(uint32_t*)&Cl[base] = lp;
                    }
                } else {
                    size_t rb = (size_t)row * N;
                    if (col < N) {
                        float v = v0;
                        if (BIAS) v += bias[col];
                        C[rb + col] = v;
                    }
                    if (col + 1 < N) {
                        float v = v1;
                        if (BIAS) v += bias[col + 1];
                        C[rb + col + 1] = v;
                    }
                }
            }
        }
    }
}

// ---------------------------------------------------------------------------
// Tensorized flash attention (causal), split-bf16 in/out, fp32 softmax.
// CTA = 128 queries x one (b,h); 8 warps x 16 queries.
// ---------------------------------------------------------------------------
#define AROWB 144
#define SMEM_ATT 73728

__global__ __launch_bounds__(256) void attn_tc(
    const __nv_bfloat16* __restrict__ qkvh,
    const __nv_bfloat16* __restrict__ qkvl,
    __nv_bfloat16* __restrict__ ah, __nv_bfloat16* __restrict__ al)
{
    extern __shared__ char smem[];
    const uint32_t sb  = (uint32_t)__cvta_generic_to_shared(smem);
    const uint32_t sQh = sb,          sQl = sb + 18432;
    const uint32_t sKh = sb + 36864,  sKl = sb + 46080;
    const uint32_t sVh = sb + 55296,  sVl = sb + 64512;
    const int tid = threadIdx.x, lane = tid & 31, w = tid >> 5;
    const int qt = gridDim.x - 1 - blockIdx.x;     // big tiles first
    const int h = blockIdx.y, b = blockIdx.z;

    #pragma unroll
    for (int i = 0; i < 4; i++) {
        int idx = tid + i * 256;
        int r = idx >> 3, q8 = idx & 7;
        size_t g = ((size_t)(b * Mseq + qt * 128 + r)) * 3072 + h * 192 + q8 * 8;
        cp16(sQh + r * AROWB + q8 * 16, qkvh + g);
        cp16(sQl + r * AROWB + q8 * 16, qkvl + g);
    }
    cp_commit();
    asm volatile("cp.async.wait_group 0;");
    __syncthreads();

    const int lr  = lane & 15;
    const int khi = (lane >> 4) << 3;

    uint32_t qfh[4][4], qfl[4][4];
    #pragma unroll
    for (int kc = 0; kc < 4; kc++) {
        uint32_t ad = (w * 16 + lr) * AROWB + (kc * 16 + khi) * 2;
        ldsm4(qfh[kc][0], qfh[kc][1], qfh[kc][2], qfh[kc][3], sQh + ad);
        ldsm4(qfl[kc][0], qfl[kc][1], qfl[kc][2], qfl[kc][3], sQl + ad);
    }

    float oacc[8][4];
    #pragma unroll
    for (int i = 0; i < 8; i++)
        #pragma unroll
        for (int j = 0; j < 4; j++) oacc[i][j] = 0.f;
    float mA = -1e30f, mB = -1e30f, lA = 0.f, lB = 0.f;

    const int q0   = qt * 128 + w * 16;
    const int rowA = q0 + (lane >> 2);
    const int rowB = rowA + 8;

    const int nkt = 2 * qt + 2;
    for (int kt = 0; kt < nkt; kt++) {
        #pragma unroll
        for (int i = 0; i < 2; i++) {
            int idx = tid + i * 256;
            int r = idx >> 3, q8 = idx & 7;
            size_t base = ((size_t)(b * Mseq + kt * 64 + r)) * 3072 + h * 192;
            uint32_t sd = r * AROWB + q8 * 16;
            cp16(sKh + sd, qkvh + base + 64  + q8 * 8);
            cp16(sKl + sd, qkvl + base + 64  + q8 * 8);
            cp16(sVh + sd, qkvh + base + 128 + q8 * 8);
            cp16(sVl + sd, qkvl + base + 128 + q8 * 8);
        }
        cp_commit();
        asm volatile("cp.async.wait_group 0;");
        __syncthreads();

        if (kt * 64 <= q0 + 15) {
            float sacc[8][4];
            #pragma unroll
            for (int i = 0; i < 8; i++)
                #pragma unroll
                for (int j = 0; j < 4; j++) sacc[i][j] = 0.f;

            #pragma unroll
            for (int kc = 0; kc < 4; kc++) {
                uint32_t kfh[4][4], kfl[4][4];
                #pragma unroll
                for (int g = 0; g < 4; g++) {
                    uint32_t ad = (g * 16 + lr) * AROWB + (kc * 16 + khi) * 2;
                    ldsm4(kfh[g][0], kfh[g][1], kfh[g][2], kfh[g][3], sKh + ad);
                    ldsm4(kfl[g][0], kfl[g][1], kfl[g][2], kfl[g][3], sKl + ad);
                }
                #pragma unroll
                for (int nt = 0; nt < 8; nt++) {
                    int g = nt >> 1, hh = nt & 1;
                    mma16816(sacc[nt], qfh[kc], kfh[g][hh], kfh[g][2 + hh]);
                    mma16816(sacc[nt], qfh[kc], kfl[g][hh], kfl[g][2 + hh]);
                    mma16816(sacc[nt], qfl[kc], kfh[g][hh], kfh[g][2 + hh]);
                }
            }

            float mxA = -1e30f, mxB = -1e30f;
            #pragma unroll
            for (int nt = 0; nt < 8; nt++) {
                int k0 = kt * 64 + nt * 8 + (lane & 3) * 2;
                float s0 = sacc[nt][0] * 0.125f;
                float s1 = sacc[nt][1] * 0.125f;
                float s2 = sacc[nt][2] * 0.125f;
                float s3 = sacc[nt][3] * 0.125f;
                if (k0     > rowA) s0 = -1e30f;
                if (k0 + 1 > rowA) s1 = -1e30f;
                if (k0     > rowB) s2 = -1e30f;
                if (k0 + 1 > rowB) s3 = -1e30f;
                sacc[nt][0] = s0; sacc[nt][1] = s1;
                sacc[nt][2] = s2; sacc[nt][3] = s3;
                mxA = fmaxf(mxA, fmaxf(s0, s1));
                mxB = fmaxf(mxB, fmaxf(s2, s3));
            }
            mxA = fmaxf(mxA, __shfl_xor_sync(0xffffffffu, mxA, 1));
            mxA = fmaxf(mxA, __shfl_xor_sync(0xffffffffu, mxA, 2));
            mxB = fmaxf(mxB, __shfl_xor_sync(0xffffffffu, mxB, 1));
            mxB = fmaxf(mxB, __shfl_xor_sync(0xffffffffu, mxB, 2));
            float mnA = fmaxf(mA, mxA), mnB = fmaxf(mB, mxB);
            float cA = __expf(mA - mnA), cB = __expf(mB - mnB);
            mA = mnA; mB = mnB;

            float sA = 0.f, sB = 0.f;
            #pragma unroll
            for (int nt = 0; nt < 8; nt++) {
                sacc[nt][0] = __expf(sacc[nt][0] - mnA);
                sacc[nt][1] = __expf(sacc[nt][1] - mnA);
                sacc[nt][2] = __expf(sacc[nt][2] - mnB);
                sacc[nt][3] = __expf(sacc[nt][3] - mnB);
                sA += sacc[nt][0] + sacc[nt][1];
                sB += sacc[nt][2] + sacc[nt][3];
            }
            sA += __shfl_xor_sync(0xffffffffu, sA, 1);
            sA += __shfl_xor_sync(0xffffffffu, sA, 2);
            sB += __shfl_xor_sync(0xffffffffu, sB, 1);
            sB += __shfl_xor_sync(0xffffffffu, sB, 2);
            lA = lA * cA + sA;
            lB = lB * cB + sB;
            #pragma unroll
            for (int nt = 0; nt < 8; nt++) {
                oacc[nt][0] *= cA; oacc[nt][1] *= cA;
                oacc[nt][2] *= cB; oacc[nt][3] *= cB;
            }

            #pragma unroll
            for (int kc = 0; kc < 4; kc++) {
                uint32_t pah[4], pal[4];
                split2(sacc[2 * kc][0],     sacc[2 * kc][1],     pah[0], pal[0]);
                split2(sacc[2 * kc][2],     sacc[2 * kc][3],     pah[1], pal[1]);
                split2(sacc[2 * kc + 1][0], sacc[2 * kc + 1][1], pah[2], pal[2]);
                split2(sacc[2 * kc + 1][2], sacc[2 * kc + 1][3], pah[3], pal[3]);

                uint32_t vfh[4][4], vfl[4][4];
                #pragma unroll
                for (int dg = 0; dg < 4; dg++) {
                    uint32_t ad = (kc * 16 + (lane & 7) + ((lane >> 4) << 3)) * AROWB
                                + (dg * 16 + ((lane >> 3) & 1) * 8) * 2;
                    ldsm4t(vfh[dg][0], vfh[dg][1], vfh[dg][2], vfh[dg][3], sVh + ad);
                    ldsm4t(vfl[dg][0], vfl[dg][1], vfl[dg][2], vfl[dg][3], sVl + ad);
                }
                #pragma unroll
                for (int nt = 0; nt < 8; nt++) {
                    int dg = nt >> 1, hh = nt & 1;
                    mma16816(oacc[nt], pah, vfh[dg][hh], vfh[dg][hh + 2]);
                    mma16816(oacc[nt], pah, vfl[dg][hh], vfl[dg][hh + 2]);
                    mma16816(oacc[nt], pal, vfh[dg][hh], vfh[dg][hh + 2]);
                }
            }
        }
        __syncthreads();
    }

    float iA = 1.f / lA, iB = 1.f / lB;
    #pragma unroll
    for (int nt = 0; nt < 8; nt++) {
        int col = h * 64 + nt * 8 + (lane & 3) * 2;
        size_t gA = ((size_t)(b * Mseq + rowA)) * Dm + col;
        size_t gB = ((size_t)(b * Mseq + rowB)) * Dm + col;
        uint32_t hp, lp;
        split2(oacc[nt][0] * iA, oacc[nt][1] * iA, hp, lp);
        *(uint32_t*)&ah[gA] = hp;
        *(uint32_t*)&al[gA] = lp;
        split2(oacc[nt][2] * iB, oacc[nt][3] * iB, hp, lp);
        *(uint32_t*)&ah[gB] = hp;
        *(uint32_t*)&al[gB] = lp;
    }
}

// ---------------------------------------------------------------------------
// Host launcher
// ---------------------------------------------------------------------------
extern "C" void kernel_launch(void* const* d_in, const int* in_sizes, int n_in,
                              void* d_out, int out_size)
{
    const int*   tokens = (const int*)  d_in[0];
    const float* emb    = (const float*)d_in[1];
    const float* pos    = (const float*)d_in[2];
    const float* ln1_s  = (const float*)d_in[3];
    const float* ln1_b  = (const float*)d_in[4];
    const float* Pi     = (const float*)d_in[5];
    const float* Po     = (const float*)d_in[6];
    const float* ln2_s  = (const float*)d_in[7];
    const float* ln2_b  = (const float*)d_in[8];
    const float* W1     = (const float*)d_in[9];
    const float* b1     = (const float*)d_in[10];
    const float* W2     = (const float*)d_in[11];
    const float* b2     = (const float*)d_in[12];
    const float* lnf_s  = (const float*)d_in[13];
    const float* lnf_b  = (const float*)d_in[14];
    const float* Wh     = (const float*)d_in[15];
    const float* bh     = (const float*)d_in[16];
    float* out = (float*)d_out;
    const int V = in_sizes[16];

    float *x;
    __nv_bfloat16 *qkvh, *qkvl, *yh, *yl, *ah, *al, *hh, *hl;
    __nv_bfloat16 *PiTh, *PiTl, *PoTh, *PoTl, *W1Th, *W1Tl, *W2Th, *W2Tl, *WhTh, *WhTl;
    cudaGetSymbolAddress((void**)&x,    g_x);
    cudaGetSymbolAddress((void**)&qkvh, g_qkvh); cudaGetSymbolAddress((void**)&qkvl, g_qkvl);
    cudaGetSymbolAddress((void**)&yh,   g_yh);   cudaGetSymbolAddress((void**)&yl,   g_yl);
    cudaGetSymbolAddress((void**)&ah,   g_ah);   cudaGetSymbolAddress((void**)&al,   g_al);
    cudaGetSymbolAddress((void**)&hh,   g_hh);   cudaGetSymbolAddress((void**)&hl,   g_hl);
    cudaGetSymbolAddress((void**)&PiTh, g_PiTh); cudaGetSymbolAddress((void**)&PiTl, g_PiTl);
    cudaGetSymbolAddress((void**)&PoTh, g_PoTh); cudaGetSymbolAddress((void**)&PoTl, g_PoTl);
    cudaGetSymbolAddress((void**)&W1Th, g_W1Th); cudaGetSymbolAddress((void**)&W1Tl, g_W1Tl);
    cudaGetSymbolAddress((void**)&W2Th, g_W2Th); cudaGetSymbolAddress((void**)&W2Tl, g_W2Tl);
    cudaGetSymbolAddress((void**)&WhTh, g_WhTh); cudaGetSymbolAddress((void**)&WhTl, g_WhTl);

    cudaFuncSetAttribute(gemm_hmma<false, false, false, false, true>,
                         cudaFuncAttributeMaxDynamicSharedMemorySize, SMEM_GEMM);
    cudaFuncSetAttribute(gemm_hmma<false, true,  false, true,  false>,
                         cudaFuncAttributeMaxDynamicSharedMemorySize, SMEM_GEMM);
    cudaFuncSetAttribute(gemm_hmma<true,  false, true,  false, true>,
                         cudaFuncAttributeMaxDynamicSharedMemorySize, SMEM_GEMM);
    cudaFuncSetAttribute(gemm_hmma<true,  true,  false, true,  false>,
                         cudaFuncAttributeMaxDynamicSharedMemorySize, SMEM_GEMM);
    cudaFuncSetAttribute(gemm_hmma<true,  false, false, true,  false>,
                         cudaFuncAttributeMaxDynamicSharedMemorySize, SMEM_GEMM);
    cudaFuncSetAttribute(attn_tc,
                         cudaFuncAttributeMaxDynamicSharedMemorySize, SMEM_ATT);

    dim3 cblk(32, 8);
    // weight conversion (transpose + split), layered over z
    convT_kernel<<<dim3(96, 32, Ll), cblk>>>(Pi, PiTh, PiTl, Dm, 3 * Dm,
                                             (size_t)Dm * 3 * Dm, (size_t)3 * Dm * Dm);
    convT_kernel<<<dim3(32, 32, Ll), cblk>>>(Po, PoTh, PoTl, Dm, Dm,
                                             (size_t)Dm * Dm, (size_t)Dm * Dm);
    convT_kernel<<<dim3(128, 32, Ll), cblk>>>(W1, W1Th, W1Tl, Dm, 4 * Dm,
                                              (size_t)Dm * 4 * Dm, (size_t)4 * Dm * Dm);
    convT_kernel<<<dim3(32, 128, Ll), cblk>>>(W2, W2Th, W2Tl, 4 * Dm, Dm,
                                              (size_t)4 * Dm * Dm, (size_t)4 * Dm * Dm);
    convT_kernel<<<dim3(VPAD / 32, 32, 1), cblk>>>(Wh, WhTh, WhTl, Dm, V, 0, 0);

    embed_kernel<<<NTOK, 256>>>(tokens, emb, pos, x);

    for (int l = 0; l < Ll; l++) {
        ln_kernel<<<NTOK, 256>>>(x, yh, yl, ln1_s + l * Dm, ln1_b + l * Dm);
        gemm_hmma<false, false, false, false, true><<<dim3(16, 24), 128, SMEM_GEMM>>>(
            yh, yl, PiTh + (size_t)l * 3 * Dm * Dm, PiTl + (size_t)l * 3 * Dm * Dm,
            nullptr, nullptr, nullptr, qkvh, qkvl, 3 * Dm, Dm);
        attn_tc<<<dim3(8, Hh, Bn), 256, SMEM_ATT>>>(qkvh, qkvl, ah, al);
        gemm_hmma<false, true, false, true, false><<<dim3(16, 8), 128, SMEM_GEMM>>>(
            ah, al, PoTh + (size_t)l * Dm * Dm, PoTl + (size_t)l * Dm * Dm,
            nullptr, x, x, nullptr, nullptr, Dm, Dm);
        ln_kernel<<<NTOK, 256>>>(x, yh, yl, ln2_s + l * Dm, ln2_b + l * Dm);
        gemm_hmma<true, false, true, false, true><<<dim3(16, 32), 128, SMEM_GEMM>>>(
            yh, yl, W1Th + (size_t)l * 4 * Dm * Dm, W1Tl + (size_t)l * 4 * Dm * Dm,
            b1 + (size_t)l * 4 * Dm, nullptr, nullptr, hh, hl, 4 * Dm, Dm);
        gemm_hmma<true, true, false, true, false><<<dim3(16, 8), 128, SMEM_GEMM>>>(
            hh, hl, W2Th + (size_t)l * 4 * Dm * Dm, W2Tl + (size_t)l * 4 * Dm * Dm,
            b2 + (size_t)l * Dm, x, x, nullptr, nullptr, Dm, 4 * Dm);
    }

    ln_kernel<<<NTOK, 256>>>(x, yh, yl, lnf_s, lnf_b);
    gemm_hmma<true, false, false, true, false><<<dim3(16, VPAD / 128), 128, SMEM_GEMM>>>(
        yh, yl, WhTh, WhTl, bh, nullptr, out, nullptr, nullptr, V, Dm);
}

// round 7
// speedup vs baseline: 4.1583x; 1.3841x over previous
#include <cuda_runtime.h>
#include <cuda_fp16.h>
#include <cstdint>
#include <cstddef>

// ---------------------------------------------------------------------------
// GPT-2 forward on GB300 (sm_103 base target): 2-pass fp16 HMMA GEMMs
// (x_fp16 * (wh + wl), weights exactly split) + fp16 HMMA flash attention.
// B=2, M=1024, D=1024, H=16, K=64, L=4, V=50257.
// ---------------------------------------------------------------------------

#define Bn 2
#define Mseq 1024
#define Dm 1024
#define Hh 16
#define Ll 4
#define NTOK 2048
#define VPAD 50304            // 50257 padded to multiple of 128

// ------------------------------- scratch ----------------------------------
__device__ float g_x[NTOK * Dm];                      // residual (fp32)
__device__ __half g_qkvh[NTOK * 3 * Dm], g_qkvl[NTOK * 3 * Dm];   // qkv split
__device__ __half g_y[NTOK * Dm];                     // LN out (single fp16)
__device__ __half g_a[NTOK * Dm];                     // attn out (single fp16)
__device__ __half g_h[NTOK * 4 * Dm];                 // MLP hidden (single)
// transposed+split weights: [N][K] K-major, fp16 hi/lo
__device__ __half g_PiTh[Ll * 3 * Dm * Dm], g_PiTl[Ll * 3 * Dm * Dm];
__device__ __half g_PoTh[Ll * Dm * Dm],     g_PoTl[Ll * Dm * Dm];
__device__ __half g_W1Th[Ll * 4 * Dm * Dm], g_W1Tl[Ll * 4 * Dm * Dm];
__device__ __half g_W2Th[Ll * 4 * Dm * Dm], g_W2Tl[Ll * 4 * Dm * Dm];
__device__ __half g_WhTh[(size_t)VPAD * Dm], g_WhTl[(size_t)VPAD * Dm];

// ----------------------------- PTX helpers --------------------------------
__device__ __forceinline__ void ldsm4(uint32_t& r0, uint32_t& r1,
                                      uint32_t& r2, uint32_t& r3, uint32_t addr)
{
    asm volatile("ldmatrix.sync.aligned.m8n8.x4.shared.b16 {%0,%1,%2,%3}, [%4];"
                 : "=r"(r0), "=r"(r1), "=r"(r2), "=r"(r3) : "r"(addr));
}
__device__ __forceinline__ void ldsm4t(uint32_t& r0, uint32_t& r1,
                                       uint32_t& r2, uint32_t& r3, uint32_t addr)
{
    asm volatile("ldmatrix.sync.aligned.m8n8.x4.trans.shared.b16 {%0,%1,%2,%3}, [%4];"
                 : "=r"(r0), "=r"(r1), "=r"(r2), "=r"(r3) : "r"(addr));
}
__device__ __forceinline__ void mma16816(float* d, const uint32_t* a,
                                         uint32_t b0, uint32_t b1)
{
    asm volatile("mma.sync.aligned.m16n8k16.row.col.f32.f16.f16.f32 "
                 "{%0,%1,%2,%3}, {%4,%5,%6,%7}, {%8,%9}, {%0,%1,%2,%3};"
                 : "+f"(d[0]), "+f"(d[1]), "+f"(d[2]), "+f"(d[3])
                 : "r"(a[0]), "r"(a[1]), "r"(a[2]), "r"(a[3]), "r"(b0), "r"(b1));
}
__device__ __forceinline__ void cp16(uint32_t sdst, const void* gsrc)
{
    asm volatile("cp.async.cg.shared.global [%0], [%1], 16;"
                 :: "r"(sdst), "l"(gsrc));
}
__device__ __forceinline__ void cp_commit() {
    asm volatile("cp.async.commit_group;");
}
__device__ __forceinline__ uint32_t pack2h(float a, float b)
{
    __half2 h = __floats2half2_rn(a, b);
    return *(uint32_t*)&h;
}
// split a pair of floats into hi/lo fp16x2 registers
__device__ __forceinline__ void split2h(float a, float b, uint32_t& hi, uint32_t& lo)
{
    __half2 h = __floats2half2_rn(a, b);
    float ra = a - __half2float(__low2half(h));
    float rb = b - __half2float(__high2half(h));
    __half2 l = __floats2half2_rn(ra, rb);
    hi = *(uint32_t*)&h;
    lo = *(uint32_t*)&l;
}

// ---------------------------------------------------------------------------
// Embedding
// ---------------------------------------------------------------------------
__global__ void embed_kernel(const int* __restrict__ tokens,
                             const float* __restrict__ emb,
                             const float* __restrict__ pos,
                             float* __restrict__ x)
{
    int idx = blockIdx.x * blockDim.x + threadIdx.x;
    int row = idx >> 8;
    int d4  = idx & 255;
    int m   = row & (Mseq - 1);
    int t   = tokens[row];
    float4 e = ((const float4*)emb)[(size_t)t * 256 + d4];
    float4 p = ((const float4*)pos)[(size_t)m * 256 + d4];
    float4 o;
    o.x = e.x + p.x; o.y = e.y + p.y; o.z = e.z + p.z; o.w = e.w + p.w;
    ((float4*)x)[idx] = o;
}

// ---------------------------------------------------------------------------
// Transpose + split: W[K,N] fp32 -> Th/Tl [Nrows][K] fp16 (rows >= N zeroed).
// ---------------------------------------------------------------------------
__global__ void convT_kernel(const float* __restrict__ W,
                             __half* __restrict__ Th,
                             __half* __restrict__ Tl,
                             int K, int N, size_t wstr, size_t tstr)
{
    __shared__ float t[32][33];
    W  += (size_t)blockIdx.z * wstr;
    Th += (size_t)blockIdx.z * tstr;
    Tl += (size_t)blockIdx.z * tstr;
    int n0 = blockIdx.x * 32, k0 = blockIdx.y * 32;
    int tx = threadIdx.x, ty = threadIdx.y;
    #pragma unroll
    for (int i = 0; i < 32; i += 8) {
        int k = k0 + ty + i, n = n0 + tx;
        t[ty + i][tx] = (n < N) ? W[(size_t)k * N + n] : 0.f;
    }
    __syncthreads();
    const int tid = ty * 32 + tx;
    #pragma unroll
    for (int i = 0; i < 2; i++) {
        int e  = tid + i * 256;
        int n  = e >> 4;
        int kp = e & 15;
        float v0 = t[2 * kp][n], v1 = t[2 * kp + 1][n];
        uint32_t hp, lp;
        split2h(v0, v1, hp, lp);
        size_t o = (size_t)(n0 + n) * K + k0 + 2 * kp;
        *(uint32_t*)&Th[o] = hp;
        *(uint32_t*)&Tl[o] = lp;
    }
}

// ---------------------------------------------------------------------------
// LayerNorm -> single fp16
// ---------------------------------------------------------------------------
__device__ __forceinline__ float blockReduceSum(float val)
{
    __shared__ float sh[8];
    __shared__ float tot;
    int lane = threadIdx.x & 31, wid = threadIdx.x >> 5;
    #pragma unroll
    for (int o = 16; o; o >>= 1) val += __shfl_down_sync(0xffffffffu, val, o);
    if (!lane) sh[wid] = val;
    __syncthreads();
    if (threadIdx.x < 32) {
        float v = (threadIdx.x < 8) ? sh[threadIdx.x] : 0.f;
        #pragma unroll
        for (int o = 4; o; o >>= 1) v += __shfl_down_sync(0xffffffffu, v, o);
        if (!threadIdx.x) tot = v;
    }
    __syncthreads();
    return tot;
}

__global__ void ln_kernel(const float* __restrict__ x,
                          __half* __restrict__ y,
                          const float* __restrict__ s, const float* __restrict__ b)
{
    int row = blockIdx.x, tid = threadIdx.x;
    const float* xr = x + (size_t)row * Dm;
    float v[4];
    #pragma unroll
    for (int i = 0; i < 4; i++) v[i] = xr[tid + 256 * i];
    float mu = blockReduceSum(v[0] + v[1] + v[2] + v[3]) * (1.f / Dm);
    float sq = 0.f;
    #pragma unroll
    for (int i = 0; i < 4; i++) { float d = v[i] - mu; sq += d * d; }
    float var = blockReduceSum(sq) * (1.f / Dm);
    float rs = rsqrtf(var + 1e-5f);
    #pragma unroll
    for (int i = 0; i < 4; i++) {
        int c = tid + 256 * i;
        float val = (v[i] - mu) * rs * s[c] + b[c];
        y[(size_t)row * Dm + c] = __float2half(val);
    }
}

__device__ __forceinline__ float gelu_new(float v)
{
    float u = 0.7978845608028654f * (v + 0.044715f * v * v * v);
    return 0.5f * v * (1.f + tanhf(u));
}

// ---------------------------------------------------------------------------
// 2-pass fp16 HMMA GEMM: C[M,N] = A[M,K] @ (Bh+Bl)[N,K]^T  (A single fp16)
// CTA tile 128x128, BK=32, 128 threads (4 warps, 64x64 warp tile), 2 CTA/SM.
// ---------------------------------------------------------------------------
#define LDB 80
#define MATB (128 * LDB)
#define STG  (3 * MATB)        // A, Bh, Bl
#define SMEM_GEMM (2 * STG)    // 61440

template <bool BIAS, bool RES, bool GELU, bool OUTF32, bool SPLIT, bool OUTH>
__global__ __launch_bounds__(128, 2) void gemm_hmma(
    const __half* __restrict__ A,
    const __half* __restrict__ Bh, const __half* __restrict__ Bl,
    const float* __restrict__ bias, const float* __restrict__ Res,
    float* __restrict__ C, __half* __restrict__ Ch,
    __half* __restrict__ Cl, int N, int K)
{
    extern __shared__ char smem[];
    const uint32_t sb = (uint32_t)__cvta_generic_to_shared(smem);
    const int tid  = threadIdx.x;
    const int lane = tid & 31;
    const int wid  = tid >> 5;
    const int bm = blockIdx.x * 128;
    const int bn = blockIdx.y * 128;
    const int wm = (wid & 1) * 64;
    const int wn = (wid >> 1) * 64;

    float acc[4][8][4];
    #pragma unroll
    for (int i = 0; i < 4; i++)
        #pragma unroll
        for (int j = 0; j < 8; j++)
            #pragma unroll
            for (int k = 0; k < 4; k++) acc[i][j][k] = 0.f;

    auto load_stage = [&](int c, int s) {
        const int kc = c * 32;
        const uint32_t st = sb + s * STG;
        #pragma unroll
        for (int i = 0; i < 4; i++) {
            int idx = tid + i * 128;          // 0..511
            int r = idx >> 2, q = idx & 3;
            uint32_t so = st + r * LDB + q * 16;
            size_t ga = (size_t)(bm + r) * K + kc + q * 8;
            cp16(so, A + ga);
            size_t gb = (size_t)(bn + r) * K + kc + q * 8;
            cp16(so + MATB,     Bh + gb);
            cp16(so + 2 * MATB, Bl + gb);
        }
        cp_commit();
    };

    const int nk = K / 32;
    load_stage(0, 0);

    const int lr  = lane & 15;
    const int kc2 = (lane >> 4) << 3;

    for (int c = 0; c < nk; c++) {
        const int s = c & 1;
        if (c + 1 < nk) {
            load_stage(c + 1, s ^ 1);
            asm volatile("cp.async.wait_group 1;");
        } else {
            asm volatile("cp.async.wait_group 0;");
        }
        __syncthreads();

        const uint32_t st = sb + s * STG;
        #pragma unroll
        for (int ks = 0; ks < 2; ks++) {
            const uint32_t ao = st + (wm + lr) * LDB + (ks * 16 + kc2) * 2;
            const uint32_t bo = st + MATB + (wn + lr) * LDB + (ks * 16 + kc2) * 2;
            uint32_t af[4][4], bh[4][4], bl[4][4];
            #pragma unroll
            for (int mt = 0; mt < 4; mt++)
                ldsm4(af[mt][0], af[mt][1], af[mt][2], af[mt][3], ao + mt * 16 * LDB);
            #pragma unroll
            for (int g = 0; g < 4; g++)
                ldsm4(bh[g][0], bh[g][1], bh[g][2], bh[g][3], bo + g * 16 * LDB);
            #pragma unroll
            for (int g = 0; g < 4; g++)
                ldsm4(bl[g][0], bl[g][1], bl[g][2], bl[g][3],
                      bo + MATB + g * 16 * LDB);

            #pragma unroll
            for (int mt = 0; mt < 4; mt++)
                #pragma unroll
                for (int nt = 0; nt < 8; nt++) {
                    int g = nt >> 1, h = nt & 1;
                    mma16816(acc[mt][nt], af[mt], bh[g][h], bh[g][2 + h]);
                    mma16816(acc[mt][nt], af[mt], bl[g][h], bl[g][2 + h]);
                }
        }
        __syncthreads();
    }

    const bool headN = (N & 1) != 0;
    #pragma unroll
    for (int mt = 0; mt < 4; mt++) {
        #pragma unroll
        for (int nt = 0; nt < 8; nt++) {
            int row0 = bm + wm + mt * 16 + (lane >> 2);
            int col  = bn + wn + nt * 8 + (lane & 3) * 2;
            #pragma unroll
            for (int half = 0; half < 2; half++) {
                int row = row0 + half * 8;
                float v0 = acc[mt][nt][half * 2];
                float v1 = acc[mt][nt][half * 2 + 1];
                if (!headN) {
                    size_t base = (size_t)row * N + col;
                    if (BIAS) { v0 += bias[col]; v1 += bias[col + 1]; }
                    if (GELU) { v0 = gelu_new(v0); v1 = gelu_new(v1); }
                    if (RES) {
                        float2 r = *(const float2*)&Res[base];
                        v0 += r.x; v1 += r.y;
                    }
                    if (OUTF32) {
                        float2 o; o.x = v0; o.y = v1;
                        *(float2*)&C[base] = o;
                    }
                    if (SPLIT) {
                        uint32_t hp, lp;
                        split2h(v0, v1, hp, lp);
                        *(uint32_t*)&Ch[base] = hp;
                        *(uint32_t*)&Cl[base] = lp;
                    }
                    if (OUTH) {
                        *(uint32_t*)&Ch[base] = pack2h(v0, v1);
                    }
                } else {
                    size_t rb = (size_t)row * N;
                    if (col < N) {
                        float v = v0;
                        if (BIAS) v += bias[col];
                        C[rb + col] = v;
                    }
                    if (col + 1 < N) {
                        float v = v1;
                        if (BIAS) v += bias[col + 1];
                        C[rb + col + 1] = v;
                    }
                }
            }
        }
    }
}

// ---------------------------------------------------------------------------
// fp16 flash attention (causal): Q,P single fp16; K,V split fp16 (2-pass).
// CTA = 128 queries x one (b,h); 8 warps x 16 queries; fp32 softmax.
// ---------------------------------------------------------------------------
#define AROWB 144
#define SMEM_ATT 55296

__global__ __launch_bounds__(256) void attn_tc(
    const __half* __restrict__ qkvh,
    const __half* __restrict__ qkvl,
    __half* __restrict__ aout)
{
    extern __shared__ char smem[];
    const uint32_t sb  = (uint32_t)__cvta_generic_to_shared(smem);
    const uint32_t sQ  = sb;
    const uint32_t sKh = sb + 18432, sKl = sb + 27648;
    const uint32_t sVh = sb + 36864, sVl = sb + 46080;
    const int tid = threadIdx.x, lane = tid & 31, w = tid >> 5;
    const int qt = gridDim.x - 1 - blockIdx.x;     // big tiles first
    const int h = blockIdx.y, b = blockIdx.z;

    #pragma unroll
    for (int i = 0; i < 4; i++) {
        int idx = tid + i * 256;            // 0..1023
        int r = idx >> 3, q8 = idx & 7;
        size_t g = ((size_t)(b * Mseq + qt * 128 + r)) * 3072 + h * 192 + q8 * 8;
        cp16(sQ + r * AROWB + q8 * 16, qkvh + g);
    }
    cp_commit();
    asm volatile("cp.async.wait_group 0;");
    __syncthreads();

    const int lr  = lane & 15;
    const int khi = (lane >> 4) << 3;

    uint32_t qf[4][4];
    #pragma unroll
    for (int kc = 0; kc < 4; kc++) {
        uint32_t ad = (w * 16 + lr) * AROWB + (kc * 16 + khi) * 2;
        ldsm4(qf[kc][0], qf[kc][1], qf[kc][2], qf[kc][3], sQ + ad);
    }

    float oacc[8][4];
    #pragma unroll
    for (int i = 0; i < 8; i++)
        #pragma unroll
        for (int j = 0; j < 4; j++) oacc[i][j] = 0.f;
    float mA = -1e30f, mB = -1e30f, lA = 0.f, lB = 0.f;

    const int q0   = qt * 128 + w * 16;
    const int rowA = q0 + (lane >> 2);
    const int rowB = rowA + 8;

    const int nkt = 2 * qt + 2;
    for (int kt = 0; kt < nkt; kt++) {
        #pragma unroll
        for (int i = 0; i < 2; i++) {
            int idx = tid + i * 256;        // 0..511
            int r = idx >> 3, q8 = idx & 7;
            size_t base = ((size_t)(b * Mseq + kt * 64 + r)) * 3072 + h * 192;
            uint32_t sd = r * AROWB + q8 * 16;
            cp16(sKh + sd, qkvh + base + 64  + q8 * 8);
            cp16(sKl + sd, qkvl + base + 64  + q8 * 8);
            cp16(sVh + sd, qkvh + base + 128 + q8 * 8);
            cp16(sVl + sd, qkvl + base + 128 + q8 * 8);
        }
        cp_commit();
        asm volatile("cp.async.wait_group 0;");
        __syncthreads();

        if (kt * 64 <= q0 + 15) {
            float sacc[8][4];
            #pragma unroll
            for (int i = 0; i < 8; i++)
                #pragma unroll
                for (int j = 0; j < 4; j++) sacc[i][j] = 0.f;

            #pragma unroll
            for (int kc = 0; kc < 4; kc++) {
                uint32_t kfh[4][4], kfl[4][4];
                #pragma unroll
                for (int g = 0; g < 4; g++) {
                    uint32_t ad = (g * 16 + lr) * AROWB + (kc * 16 + khi) * 2;
                    ldsm4(kfh[g][0], kfh[g][1], kfh[g][2], kfh[g][3], sKh + ad);
                    ldsm4(kfl[g][0], kfl[g][1], kfl[g][2], kfl[g][3], sKl + ad);
                }
                #pragma unroll
                for (int nt = 0; nt < 8; nt++) {
                    int g = nt >> 1, hh = nt & 1;
                    mma16816(sacc[nt], qf[kc], kfh[g][hh], kfh[g][2 + hh]);
                    mma16816(sacc[nt], qf[kc], kfl[g][hh], kfl[g][2 + hh]);
                }
            }

            float mxA = -1e30f, mxB = -1e30f;
            #pragma unroll
            for (int nt = 0; nt < 8; nt++) {
                int k0 = kt * 64 + nt * 8 + (lane & 3) * 2;
                float s0 = sacc[nt][0] * 0.125f;
                float s1 = sacc[nt][1] * 0.125f;
                float s2 = sacc[nt][2] * 0.125f;
                float s3 = sacc[nt][3] * 0.125f;
                if (k0     > rowA) s0 = -1e30f;
                if (k0 + 1 > rowA) s1 = -1e30f;
                if (k0     > rowB) s2 = -1e30f;
                if (k0 + 1 > rowB) s3 = -1e30f;
                sacc[nt][0] = s0; sacc[nt][1] = s1;
                sacc[nt][2] = s2; sacc[nt][3] = s3;
                mxA = fmaxf(mxA, fmaxf(s0, s1));
                mxB = fmaxf(mxB, fmaxf(s2, s3));
            }
            mxA = fmaxf(mxA, __shfl_xor_sync(0xffffffffu, mxA, 1));
            mxA = fmaxf(mxA, __shfl_xor_sync(0xffffffffu, mxA, 2));
            mxB = fmaxf(mxB, __shfl_xor_sync(0xffffffffu, mxB, 1));
            mxB = fmaxf(mxB, __shfl_xor_sync(0xffffffffu, mxB, 2));
            float mnA = fmaxf(mA, mxA), mnB = fmaxf(mB, mxB);
            float cA = __expf(mA - mnA), cB = __expf(mB - mnB);
            mA = mnA; mB = mnB;

            float sA = 0.f, sB = 0.f;
            #pragma unroll
            for (int nt = 0; nt < 8; nt++) {
                sacc[nt][0] = __expf(sacc[nt][0] - mnA);
                sacc[nt][1] = __expf(sacc[nt][1] - mnA);
                sacc[nt][2] = __expf(sacc[nt][2] - mnB);
                sacc[nt][3] = __expf(sacc[nt][3] - mnB);
                sA += sacc[nt][0] + sacc[nt][1];
                sB += sacc[nt][2] + sacc[nt][3];
            }
            sA += __shfl_xor_sync(0xffffffffu, sA, 1);
            sA += __shfl_xor_sync(0xffffffffu, sA, 2);
            sB += __shfl_xor_sync(0xffffffffu, sB, 1);
            sB += __shfl_xor_sync(0xffffffffu, sB, 2);
            lA = lA * cA + sA;
            lB = lB * cB + sB;
            #pragma unroll
            for (int nt = 0; nt < 8; nt++) {
                oacc[nt][0] *= cA; oacc[nt][1] *= cA;
                oacc[nt][2] *= cB; oacc[nt][3] *= cB;
            }

            #pragma unroll
            for (int kc = 0; kc < 4; kc++) {
                uint32_t ph[4];
                ph[0] = pack2h(sacc[2 * kc][0],     sacc[2 * kc][1]);
                ph[1] = pack2h(sacc[2 * kc][2],     sacc[2 * kc][3]);
                ph[2] = pack2h(sacc[2 * kc + 1][0], sacc[2 * kc + 1][1]);
                ph[3] = pack2h(sacc[2 * kc + 1][2], sacc[2 * kc + 1][3]);

                uint32_t vfh[4][4], vfl[4][4];
                #pragma unroll
                for (int dg = 0; dg < 4; dg++) {
                    uint32_t ad = (kc * 16 + (lane & 7) + ((lane >> 4) << 3)) * AROWB
                                + (dg * 16 + ((lane >> 3) & 1) * 8) * 2;
                    ldsm4t(vfh[dg][0], vfh[dg][1], vfh[dg][2], vfh[dg][3], sVh + ad);
                    ldsm4t(vfl[dg][0], vfl[dg][1], vfl[dg][2], vfl[dg][3], sVl + ad);
                }
                #pragma unroll
                for (int nt = 0; nt < 8; nt++) {
                    int dg = nt >> 1, hh = nt & 1;
                    mma16816(oacc[nt], ph, vfh[dg][hh], vfh[dg][hh + 2]);
                    mma16816(oacc[nt], ph, vfl[dg][hh], vfl[dg][hh + 2]);
                }
            }
        }
        __syncthreads();
    }

    float iA = 1.f / lA, iB = 1.f / lB;
    #pragma unroll
    for (int nt = 0; nt < 8; nt++) {
        int col = h * 64 + nt * 8 + (lane & 3) * 2;
        size_t gA = ((size_t)(b * Mseq + rowA)) * Dm + col;
        size_t gB = ((size_t)(b * Mseq + rowB)) * Dm + col;
        *(uint32_t*)&aout[gA] = pack2h(oacc[nt][0] * iA, oacc[nt][1] * iA);
        *(uint32_t*)&aout[gB] = pack2h(oacc[nt][2] * iB, oacc[nt][3] * iB);
    }
}

// ---------------------------------------------------------------------------
// Host launcher
// ---------------------------------------------------------------------------
extern "C" void kernel_launch(void* const* d_in, const int* in_sizes, int n_in,
                              void* d_out, int out_size)
{
    const int*   tokens = (const int*)  d_in[0];
    const float* emb    = (const float*)d_in[1];
    const float* pos    = (const float*)d_in[2];
    const float* ln1_s  = (const float*)d_in[3];
    const float* ln1_b  = (const float*)d_in[4];
    const float* Pi     = (const float*)d_in[5];
    const float* Po     = (const float*)d_in[6];
    const float* ln2_s  = (const float*)d_in[7];
    const float* ln2_b  = (const float*)d_in[8];
    const float* W1     = (const float*)d_in[9];
    const float* b1     = (const float*)d_in[10];
    const float* W2     = (const float*)d_in[11];
    const float* b2     = (const float*)d_in[12];
    const float* lnf_s  = (const float*)d_in[13];
    const float* lnf_b  = (const float*)d_in[14];
    const float* Wh     = (const float*)d_in[15];
    const float* bh     = (const float*)d_in[16];
    float* out = (float*)d_out;
    const int V = in_sizes[16];

    float *x;
    __half *qkvh, *qkvl, *y, *a, *hbuf;
    __half *PiTh, *PiTl, *PoTh, *PoTl, *W1Th, *W1Tl, *W2Th, *W2Tl, *WhTh, *WhTl;
    cudaGetSymbolAddress((void**)&x,    g_x);
    cudaGetSymbolAddress((void**)&qkvh, g_qkvh); cudaGetSymbolAddress((void**)&qkvl, g_qkvl);
    cudaGetSymbolAddress((void**)&y,    g_y);
    cudaGetSymbolAddress((void**)&a,    g_a);
    cudaGetSymbolAddress((void**)&hbuf, g_h);
    cudaGetSymbolAddress((void**)&PiTh, g_PiTh); cudaGetSymbolAddress((void**)&PiTl, g_PiTl);
    cudaGetSymbolAddress((void**)&PoTh, g_PoTh); cudaGetSymbolAddress((void**)&PoTl, g_PoTl);
    cudaGetSymbolAddress((void**)&W1Th, g_W1Th); cudaGetSymbolAddress((void**)&W1Tl, g_W1Tl);
    cudaGetSymbolAddress((void**)&W2Th, g_W2Th); cudaGetSymbolAddress((void**)&W2Tl, g_W2Tl);
    cudaGetSymbolAddress((void**)&WhTh, g_WhTh); cudaGetSymbolAddress((void**)&WhTl, g_WhTl);

    cudaFuncSetAttribute(gemm_hmma<false, false, false, false, true,  false>,
                         cudaFuncAttributeMaxDynamicSharedMemorySize, SMEM_GEMM);
    cudaFuncSetAttribute(gemm_hmma<false, true,  false, true,  false, false>,
                         cudaFuncAttributeMaxDynamicSharedMemorySize, SMEM_GEMM);
    cudaFuncSetAttribute(gemm_hmma<true,  false, true,  false, false, true>,
                         cudaFuncAttributeMaxDynamicSharedMemorySize, SMEM_GEMM);
    cudaFuncSetAttribute(gemm_hmma<true,  true,  false, true,  false, false>,
                         cudaFuncAttributeMaxDynamicSharedMemorySize, SMEM_GEMM);
    cudaFuncSetAttribute(gemm_hmma<true,  false, false, true,  false, false>,
                         cudaFuncAttributeMaxDynamicSharedMemorySize, SMEM_GEMM);
    cudaFuncSetAttribute(attn_tc,
                         cudaFuncAttributeMaxDynamicSharedMemorySize, SMEM_ATT);

    dim3 cblk(32, 8);
    convT_kernel<<<dim3(96, 32, Ll), cblk>>>(Pi, PiTh, PiTl, Dm, 3 * Dm,
                                             (size_t)Dm * 3 * Dm, (size_t)3 * Dm * Dm);
    convT_kernel<<<dim3(32, 32, Ll), cblk>>>(Po, PoTh, PoTl, Dm, Dm,
                                             (size_t)Dm * Dm, (size_t)Dm * Dm);
    convT_kernel<<<dim3(128, 32, Ll), cblk>>>(W1, W1Th, W1Tl, Dm, 4 * Dm,
                                              (size_t)Dm * 4 * Dm, (size_t)4 * Dm * Dm);
    convT_kernel<<<dim3(32, 128, Ll), cblk>>>(W2, W2Th, W2Tl, 4 * Dm, Dm,
                                              (size_t)4 * Dm * Dm, (size_t)4 * Dm * Dm);
    convT_kernel<<<dim3(VPAD / 32, 32, 1), cblk>>>(Wh, WhTh, WhTl, Dm, V, 0, 0);

    embed_kernel<<<NTOK, 256>>>(tokens, emb, pos, x);

    for (int l = 0; l < Ll; l++) {
        ln_kernel<<<NTOK, 256>>>(x, y, ln1_s + l * Dm, ln1_b + l * Dm);
        gemm_hmma<false, false, false, false, true, false><<<dim3(16, 24), 128, SMEM_GEMM>>>(
            y, PiTh + (size_t)l * 3 * Dm * Dm, PiTl + (size_t)l * 3 * Dm * Dm,
            nullptr, nullptr, nullptr, qkvh, qkvl, 3 * Dm, Dm);
        attn_tc<<<dim3(8, Hh, Bn), 256, SMEM_ATT>>>(qkvh, qkvl, a);
        gemm_hmma<false, true, false, true, false, false><<<dim3(16, 8), 128, SMEM_GEMM>>>(
            a, PoTh + (size_t)l * Dm * Dm, PoTl + (size_t)l * Dm * Dm,
            nullptr, x, x, nullptr, nullptr, Dm, Dm);
        ln_kernel<<<NTOK, 256>>>(x, y, ln2_s + l * Dm, ln2_b + l * Dm);
        gemm_hmma<true, false, true, false, false, true><<<dim3(16, 32), 128, SMEM_GEMM>>>(
            y, W1Th + (size_t)l * 4 * Dm * Dm, W1Tl + (size_t)l * 4 * Dm * Dm,
            b1 + (size_t)l * 4 * Dm, nullptr, nullptr, hbuf, nullptr, 4 * Dm, Dm);
        gemm_hmma<true, true, false, true, false, false><<<dim3(16, 8), 128, SMEM_GEMM>>>(
            hbuf, W2Th + (size_t)l * 4 * Dm * Dm, W2Tl + (size_t)l * 4 * Dm * Dm,
            b2 + (size_t)l * Dm, x, x, nullptr, nullptr, Dm, 4 * Dm);
    }

    ln_kernel<<<NTOK, 256>>>(x, y, lnf_s, lnf_b);
    gemm_hmma<true, false, false, true, false, false><<<dim3(16, VPAD / 128), 128, SMEM_GEMM>>>(
        y, WhTh, WhTl, bh, nullptr, out, nullptr, nullptr, V, Dm);
}

// round 8
// speedup vs baseline: 4.9487x; 1.1901x over previous
#include <cuda_runtime.h>
#include <cuda_fp16.h>
#include <cstdint>
#include <cstddef>

// ---------------------------------------------------------------------------
// GPT-2 forward on GB300 (sm_103 base target): fp16 HMMA GEMMs
// (2-pass exact-split weights internally, 1-pass LM head) + fp16 HMMA
// flash attention. B=2, M=1024, D=1024, H=16, K=64, L=4, V=50257.
// ---------------------------------------------------------------------------

#define Bn 2
#define Mseq 1024
#define Dm 1024
#define Hh 16
#define Ll 4
#define NTOK 2048
#define VPAD 50304            // 50257 padded to multiple of 128

// ------------------------------- scratch ----------------------------------
__device__ float g_x[NTOK * Dm];                      // residual (fp32)
__device__ __half g_qkvh[NTOK * 3 * Dm], g_qkvl[NTOK * 3 * Dm];   // qkv split
__device__ __half g_y[NTOK * Dm];                     // LN out (single fp16)
__device__ __half g_a[NTOK * Dm];                     // attn out (single fp16)
__device__ __half g_h[NTOK * 4 * Dm];                 // MLP hidden (single)
// transposed+split weights: [N][K] K-major, fp16 hi/lo
__device__ __half g_PiTh[Ll * 3 * Dm * Dm], g_PiTl[Ll * 3 * Dm * Dm];
__device__ __half g_PoTh[Ll * Dm * Dm],     g_PoTl[Ll * Dm * Dm];
__device__ __half g_W1Th[Ll * 4 * Dm * Dm], g_W1Tl[Ll * 4 * Dm * Dm];
__device__ __half g_W2Th[Ll * 4 * Dm * Dm], g_W2Tl[Ll * 4 * Dm * Dm];
__device__ __half g_WhTh[(size_t)VPAD * Dm];          // head: hi only (1-pass)

// ----------------------------- PTX helpers --------------------------------
__device__ __forceinline__ void ldsm4(uint32_t& r0, uint32_t& r1,
                                      uint32_t& r2, uint32_t& r3, uint32_t addr)
{
    asm volatile("ldmatrix.sync.aligned.m8n8.x4.shared.b16 {%0,%1,%2,%3}, [%4];"
                 : "=r"(r0), "=r"(r1), "=r"(r2), "=r"(r3) : "r"(addr));
}
__device__ __forceinline__ void ldsm4t(uint32_t& r0, uint32_t& r1,
                                       uint32_t& r2, uint32_t& r3, uint32_t addr)
{
    asm volatile("ldmatrix.sync.aligned.m8n8.x4.trans.shared.b16 {%0,%1,%2,%3}, [%4];"
                 : "=r"(r0), "=r"(r1), "=r"(r2), "=r"(r3) : "r"(addr));
}
__device__ __forceinline__ void mma16816(float* d, const uint32_t* a,
                                         uint32_t b0, uint32_t b1)
{
    asm volatile("mma.sync.aligned.m16n8k16.row.col.f32.f16.f16.f32 "
                 "{%0,%1,%2,%3}, {%4,%5,%6,%7}, {%8,%9}, {%0,%1,%2,%3};"
                 : "+f"(d[0]), "+f"(d[1]), "+f"(d[2]), "+f"(d[3])
                 : "r"(a[0]), "r"(a[1]), "r"(a[2]), "r"(a[3]), "r"(b0), "r"(b1));
}
__device__ __forceinline__ void cp16(uint32_t sdst, const void* gsrc)
{
    asm volatile("cp.async.cg.shared.global [%0], [%1], 16;"
                 :: "r"(sdst), "l"(gsrc));
}
__device__ __forceinline__ void cp_commit() {
    asm volatile("cp.async.commit_group;");
}
__device__ __forceinline__ uint32_t pack2h(float a, float b)
{
    __half2 h = __floats2half2_rn(a, b);
    return *(uint32_t*)&h;
}
// split a pair of floats into hi/lo fp16x2 registers
__device__ __forceinline__ void split2h(float a, float b, uint32_t& hi, uint32_t& lo)
{
    __half2 h = __floats2half2_rn(a, b);
    float ra = a - __half2float(__low2half(h));
    float rb = b - __half2float(__high2half(h));
    __half2 l = __floats2half2_rn(ra, rb);
    hi = *(uint32_t*)&h;
    lo = *(uint32_t*)&l;
}

// ---------------------------------------------------------------------------
// Embedding
// ---------------------------------------------------------------------------
__global__ void embed_kernel(const int* __restrict__ tokens,
                             const float* __restrict__ emb,
                             const float* __restrict__ pos,
                             float* __restrict__ x)
{
    int idx = blockIdx.x * blockDim.x + threadIdx.x;
    int row = idx >> 8;
    int d4  = idx & 255;
    int m   = row & (Mseq - 1);
    int t   = tokens[row];
    float4 e = ((const float4*)emb)[(size_t)t * 256 + d4];
    float4 p = ((const float4*)pos)[(size_t)m * 256 + d4];
    float4 o;
    o.x = e.x + p.x; o.y = e.y + p.y; o.z = e.z + p.z; o.w = e.w + p.w;
    ((float4*)x)[idx] = o;
}

// ---------------------------------------------------------------------------
// Transpose + split: W[K,N] fp32 -> Th (+Tl if non-null) [Nrows][K] fp16.
// ---------------------------------------------------------------------------
__global__ void convT_kernel(const float* __restrict__ W,
                             __half* __restrict__ Th,
                             __half* __restrict__ Tl,
                             int K, int N, size_t wstr, size_t tstr)
{
    __shared__ float t[32][33];
    W  += (size_t)blockIdx.z * wstr;
    Th += (size_t)blockIdx.z * tstr;
    if (Tl) Tl += (size_t)blockIdx.z * tstr;
    int n0 = blockIdx.x * 32, k0 = blockIdx.y * 32;
    int tx = threadIdx.x, ty = threadIdx.y;
    #pragma unroll
    for (int i = 0; i < 32; i += 8) {
        int k = k0 + ty + i, n = n0 + tx;
        t[ty + i][tx] = (n < N) ? W[(size_t)k * N + n] : 0.f;
    }
    __syncthreads();
    const int tid = ty * 32 + tx;
    #pragma unroll
    for (int i = 0; i < 2; i++) {
        int e  = tid + i * 256;
        int n  = e >> 4;
        int kp = e & 15;
        float v0 = t[2 * kp][n], v1 = t[2 * kp + 1][n];
        uint32_t hp, lp;
        split2h(v0, v1, hp, lp);
        size_t o = (size_t)(n0 + n) * K + k0 + 2 * kp;
        *(uint32_t*)&Th[o] = hp;
        if (Tl) *(uint32_t*)&Tl[o] = lp;
    }
}

// ---------------------------------------------------------------------------
// LayerNorm -> single fp16
// ---------------------------------------------------------------------------
__device__ __forceinline__ float blockReduceSum(float val)
{
    __shared__ float sh[8];
    __shared__ float tot;
    int lane = threadIdx.x & 31, wid = threadIdx.x >> 5;
    #pragma unroll
    for (int o = 16; o; o >>= 1) val += __shfl_down_sync(0xffffffffu, val, o);
    if (!lane) sh[wid] = val;
    __syncthreads();
    if (threadIdx.x < 32) {
        float v = (threadIdx.x < 8) ? sh[threadIdx.x] : 0.f;
        #pragma unroll
        for (int o = 4; o; o >>= 1) v += __shfl_down_sync(0xffffffffu, v, o);
        if (!threadIdx.x) tot = v;
    }
    __syncthreads();
    return tot;
}

__global__ void ln_kernel(const float* __restrict__ x,
                          __half* __restrict__ y,
                          const float* __restrict__ s, const float* __restrict__ b)
{
    int row = blockIdx.x, tid = threadIdx.x;
    const float* xr = x + (size_t)row * Dm;
    float v[4];
    #pragma unroll
    for (int i = 0; i < 4; i++) v[i] = xr[tid + 256 * i];
    float mu = blockReduceSum(v[0] + v[1] + v[2] + v[3]) * (1.f / Dm);
    float sq = 0.f;
    #pragma unroll
    for (int i = 0; i < 4; i++) { float d = v[i] - mu; sq += d * d; }
    float var = blockReduceSum(sq) * (1.f / Dm);
    float rs = rsqrtf(var + 1e-5f);
    #pragma unroll
    for (int i = 0; i < 4; i++) {
        int c = tid + 256 * i;
        float val = (v[i] - mu) * rs * s[c] + b[c];
        y[(size_t)row * Dm + c] = __float2half(val);
    }
}

__device__ __forceinline__ float gelu_new(float v)
{
    float u = 0.7978845608028654f * (v + 0.044715f * v * v * v);
    return 0.5f * v * (1.f + tanhf(u));
}

// ---------------------------------------------------------------------------
// fp16 HMMA GEMM: C[M,N] = A[M,K] @ (Bh[+Bl])[N,K]^T  (A single fp16)
// CTA tile 128x128, BK=32, 128 threads (4 warps, 64x64 warp tile), 2 CTA/SM.
// PASS2: include the Bl correction pass.
// ---------------------------------------------------------------------------
#define LDB 80
#define MATB (128 * LDB)
#define STG  (3 * MATB)        // A, Bh, Bl
#define SMEM_GEMM (2 * STG)    // 61440

template <bool BIAS, bool RES, bool GELU, bool OUTF32, bool SPLIT, bool OUTH,
          bool PASS2>
__global__ __launch_bounds__(128, 2) void gemm_hmma(
    const __half* __restrict__ A,
    const __half* __restrict__ Bh, const __half* __restrict__ Bl,
    const float* __restrict__ bias, const float* __restrict__ Res,
    float* __restrict__ C, __half* __restrict__ Ch,
    __half* __restrict__ Cl, int N, int K)
{
    extern __shared__ char smem[];
    const uint32_t sb = (uint32_t)__cvta_generic_to_shared(smem);
    const int tid  = threadIdx.x;
    const int lane = tid & 31;
    const int wid  = tid >> 5;
    const int bm = blockIdx.x * 128;
    const int bn = blockIdx.y * 128;
    const int wm = (wid & 1) * 64;
    const int wn = (wid >> 1) * 64;

    float acc[4][8][4];
    #pragma unroll
    for (int i = 0; i < 4; i++)
        #pragma unroll
        for (int j = 0; j < 8; j++)
            #pragma unroll
            for (int k = 0; k < 4; k++) acc[i][j][k] = 0.f;

    auto load_stage = [&](int c, int s) {
        const int kc = c * 32;
        const uint32_t st = sb + s * STG;
        #pragma unroll
        for (int i = 0; i < 4; i++) {
            int idx = tid + i * 128;          // 0..511
            int r = idx >> 2, q = idx & 3;
            uint32_t so = st + r * LDB + q * 16;
            size_t ga = (size_t)(bm + r) * K + kc + q * 8;
            cp16(so, A + ga);
            size_t gb = (size_t)(bn + r) * K + kc + q * 8;
            cp16(so + MATB, Bh + gb);
            if (PASS2) cp16(so + 2 * MATB, Bl + gb);
        }
        cp_commit();
    };

    const int nk = K / 32;
    load_stage(0, 0);

    const int lr  = lane & 15;
    const int kc2 = (lane >> 4) << 3;

    for (int c = 0; c < nk; c++) {
        const int s = c & 1;
        if (c + 1 < nk) {
            load_stage(c + 1, s ^ 1);
            asm volatile("cp.async.wait_group 1;");
        } else {
            asm volatile("cp.async.wait_group 0;");
        }
        __syncthreads();

        const uint32_t st = sb + s * STG;
        #pragma unroll
        for (int ks = 0; ks < 2; ks++) {
            const uint32_t ao = st + (wm + lr) * LDB + (ks * 16 + kc2) * 2;
            const uint32_t bo = st + MATB + (wn + lr) * LDB + (ks * 16 + kc2) * 2;
            uint32_t af[4][4], bh[4][4], bl[4][4];
            #pragma unroll
            for (int mt = 0; mt < 4; mt++)
                ldsm4(af[mt][0], af[mt][1], af[mt][2], af[mt][3], ao + mt * 16 * LDB);
            #pragma unroll
            for (int g = 0; g < 4; g++)
                ldsm4(bh[g][0], bh[g][1], bh[g][2], bh[g][3], bo + g * 16 * LDB);
            if (PASS2) {
                #pragma unroll
                for (int g = 0; g < 4; g++)
                    ldsm4(bl[g][0], bl[g][1], bl[g][2], bl[g][3],
                          bo + MATB + g * 16 * LDB);
            }

            #pragma unroll
            for (int mt = 0; mt < 4; mt++)
                #pragma unroll
                for (int nt = 0; nt < 8; nt++) {
                    int g = nt >> 1, h = nt & 1;
                    mma16816(acc[mt][nt], af[mt], bh[g][h], bh[g][2 + h]);
                    if (PASS2)
                        mma16816(acc[mt][nt], af[mt], bl[g][h], bl[g][2 + h]);
                }
        }
        __syncthreads();
    }

    const bool headN = (N & 1) != 0;
    #pragma unroll
    for (int mt = 0; mt < 4; mt++) {
        #pragma unroll
        for (int nt = 0; nt < 8; nt++) {
            int row0 = bm + wm + mt * 16 + (lane >> 2);
            int col  = bn + wn + nt * 8 + (lane & 3) * 2;
            #pragma unroll
            for (int half = 0; half < 2; half++) {
                int row = row0 + half * 8;
                float v0 = acc[mt][nt][half * 2];
                float v1 = acc[mt][nt][half * 2 + 1];
                if (!headN) {
                    size_t base = (size_t)row * N + col;
                    if (BIAS) { v0 += bias[col]; v1 += bias[col + 1]; }
                    if (GELU) { v0 = gelu_new(v0); v1 = gelu_new(v1); }
                    if (RES) {
                        float2 r = *(const float2*)&Res[base];
                        v0 += r.x; v1 += r.y;
                    }
                    if (OUTF32) {
                        float2 o; o.x = v0; o.y = v1;
                        *(float2*)&C[base] = o;
                    }
                    if (SPLIT) {
                        uint32_t hp, lp;
                        split2h(v0, v1, hp, lp);
                        *(uint32_t*)&Ch[base] = hp;
                        *(uint32_t*)&Cl[base] = lp;
                    }
                    if (OUTH) {
                        *(uint32_t*)&Ch[base] = pack2h(v0, v1);
                    }
                } else {
                    size_t rb = (size_t)row * N;
                    if (col < N) {
                        float v = v0;
                        if (BIAS) v += bias[col];
                        C[rb + col] = v;
                    }
                    if (col + 1 < N) {
                        float v = v1;
                        if (BIAS) v += bias[col + 1];
                        C[rb + col + 1] = v;
                    }
                }
            }
        }
    }
}

// ---------------------------------------------------------------------------
// fp16 flash attention (causal): Q,P single fp16; K,V split fp16 (2-pass).
// CTA = 128 queries x one (b,h); 8 warps x 16 queries; fp32 softmax.
// ---------------------------------------------------------------------------
#define AROWB 144
#define SMEM_ATT 55296

__global__ __launch_bounds__(256) void attn_tc(
    const __half* __restrict__ qkvh,
    const __half* __restrict__ qkvl,
    __half* __restrict__ aout)
{
    extern __shared__ char smem[];
    const uint32_t sb  = (uint32_t)__cvta_generic_to_shared(smem);
    const uint32_t sQ  = sb;
    const uint32_t sKh = sb + 18432, sKl = sb + 27648;
    const uint32_t sVh = sb + 36864, sVl = sb + 46080;
    const int tid = threadIdx.x, lane = tid & 31, w = tid >> 5;
    const int qt = gridDim.x - 1 - blockIdx.x;     // big tiles first
    const int h = blockIdx.y, b = blockIdx.z;

    #pragma unroll
    for (int i = 0; i < 4; i++) {
        int idx = tid + i * 256;            // 0..1023
        int r = idx >> 3, q8 = idx & 7;
        size_t g = ((size_t)(b * Mseq + qt * 128 + r)) * 3072 + h * 192 + q8 * 8;
        cp16(sQ + r * AROWB + q8 * 16, qkvh + g);
    }
    cp_commit();
    asm volatile("cp.async.wait_group 0;");
    __syncthreads();

    const int lr  = lane & 15;
    const int khi = (lane >> 4) << 3;

    uint32_t qf[4][4];
    #pragma unroll
    for (int kc = 0; kc < 4; kc++) {
        uint32_t ad = (w * 16 + lr) * AROWB + (kc * 16 + khi) * 2;
        ldsm4(qf[kc][0], qf[kc][1], qf[kc][2], qf[kc][3], sQ + ad);
    }

    float oacc[8][4];
    #pragma unroll
    for (int i = 0; i < 8; i++)
        #pragma unroll
        for (int j = 0; j < 4; j++) oacc[i][j] = 0.f;
    float mA = -1e30f, mB = -1e30f, lA = 0.f, lB = 0.f;

    const int q0   = qt * 128 + w * 16;
    const int rowA = q0 + (lane >> 2);
    const int rowB = rowA + 8;

    const int nkt = 2 * qt + 2;
    for (int kt = 0; kt < nkt; kt++) {
        #pragma unroll
        for (int i = 0; i < 2; i++) {
            int idx = tid + i * 256;        // 0..511
            int r = idx >> 3, q8 = idx & 7;
            size_t base = ((size_t)(b * Mseq + kt * 64 + r)) * 3072 + h * 192;
            uint32_t sd = r * AROWB + q8 * 16;
            cp16(sKh + sd, qkvh + base + 64  + q8 * 8);
            cp16(sKl + sd, qkvl + base + 64  + q8 * 8);
            cp16(sVh + sd, qkvh + base + 128 + q8 * 8);
            cp16(sVl + sd, qkvl + base + 128 + q8 * 8);
        }
        cp_commit();
        asm volatile("cp.async.wait_group 0;");
        __syncthreads();

        if (kt * 64 <= q0 + 15) {
            float sacc[8][4];
            #pragma unroll
            for (int i = 0; i < 8; i++)
                #pragma unroll
                for (int j = 0; j < 4; j++) sacc[i][j] = 0.f;

            #pragma unroll
            for (int kc = 0; kc < 4; kc++) {
                uint32_t kfh[4][4], kfl[4][4];
                #pragma unroll
                for (int g = 0; g < 4; g++) {
                    uint32_t ad = (g * 16 + lr) * AROWB + (kc * 16 + khi) * 2;
                    ldsm4(kfh[g][0], kfh[g][1], kfh[g][2], kfh[g][3], sKh + ad);
                    ldsm4(kfl[g][0], kfl[g][1], kfl[g][2], kfl[g][3], sKl + ad);
                }
                #pragma unroll
                for (int nt = 0; nt < 8; nt++) {
                    int g = nt >> 1, hh = nt & 1;
                    mma16816(sacc[nt], qf[kc], kfh[g][hh], kfh[g][2 + hh]);
                    mma16816(sacc[nt], qf[kc], kfl[g][hh], kfl[g][2 + hh]);
                }
            }

            float mxA = -1e30f, mxB = -1e30f;
            #pragma unroll
            for (int nt = 0; nt < 8; nt++) {
                int k0 = kt * 64 + nt * 8 + (lane & 3) * 2;
                float s0 = sacc[nt][0] * 0.125f;
                float s1 = sacc[nt][1] * 0.125f;
                float s2 = sacc[nt][2] * 0.125f;
                float s3 = sacc[nt][3] * 0.125f;
                if (k0     > rowA) s0 = -1e30f;
                if (k0 + 1 > rowA) s1 = -1e30f;
                if (k0     > rowB) s2 = -1e30f;
                if (k0 + 1 > rowB) s3 = -1e30f;
                sacc[nt][0] = s0; sacc[nt][1] = s1;
                sacc[nt][2] = s2; sacc[nt][3] = s3;
                mxA = fmaxf(mxA, fmaxf(s0, s1));
                mxB = fmaxf(mxB, fmaxf(s2, s3));
            }
            mxA = fmaxf(mxA, __shfl_xor_sync(0xffffffffu, mxA, 1));
            mxA = fmaxf(mxA, __shfl_xor_sync(0xffffffffu, mxA, 2));
            mxB = fmaxf(mxB, __shfl_xor_sync(0xffffffffu, mxB, 1));
            mxB = fmaxf(mxB, __shfl_xor_sync(0xffffffffu, mxB, 2));
            float mnA = fmaxf(mA, mxA), mnB = fmaxf(mB, mxB);
            float cA = __expf(mA - mnA), cB = __expf(mB - mnB);
            mA = mnA; mB = mnB;

            float sA = 0.f, sB = 0.f;
            #pragma unroll
            for (int nt = 0; nt < 8; nt++) {
                sacc[nt][0] = __expf(sacc[nt][0] - mnA);
                sacc[nt][1] = __expf(sacc[nt][1] - mnA);
                sacc[nt][2] = __expf(sacc[nt][2] - mnB);
                sacc[nt][3] = __expf(sacc[nt][3] - mnB);
                sA += sacc[nt][0] + sacc[nt][1];
                sB += sacc[nt][2] + sacc[nt][3];
            }
            sA += __shfl_xor_sync(0xffffffffu, sA, 1);
            sA += __shfl_xor_sync(0xffffffffu, sA, 2);
            sB += __shfl_xor_sync(0xffffffffu, sB, 1);
            sB += __shfl_xor_sync(0xffffffffu, sB, 2);
            lA = lA * cA + sA;
            lB = lB * cB + sB;
            #pragma unroll
            for (int nt = 0; nt < 8; nt++) {
                oacc[nt][0] *= cA; oacc[nt][1] *= cA;
                oacc[nt][2] *= cB; oacc[nt][3] *= cB;
            }

            #pragma unroll
            for (int kc = 0; kc < 4; kc++) {
                uint32_t ph[4];
                ph[0] = pack2h(sacc[2 * kc][0],     sacc[2 * kc][1]);
                ph[1] = pack2h(sacc[2 * kc][2],     sacc[2 * kc][3]);
                ph[2] = pack2h(sacc[2 * kc + 1][0], sacc[2 * kc + 1][1]);
                ph[3] = pack2h(sacc[2 * kc + 1][2], sacc[2 * kc + 1][3]);

                uint32_t vfh[4][4], vfl[4][4];
                #pragma unroll
                for (int dg = 0; dg < 4; dg++) {
                    uint32_t ad = (kc * 16 + (lane & 7) + ((lane >> 4) << 3)) * AROWB
                                + (dg * 16 + ((lane >> 3) & 1) * 8) * 2;
                    ldsm4t(vfh[dg][0], vfh[dg][1], vfh[dg][2], vfh[dg][3], sVh + ad);
                    ldsm4t(vfl[dg][0], vfl[dg][1], vfl[dg][2], vfl[dg][3], sVl + ad);
                }
                #pragma unroll
                for (int nt = 0; nt < 8; nt++) {
                    int dg = nt >> 1, hh = nt & 1;
                    mma16816(oacc[nt], ph, vfh[dg][hh], vfh[dg][hh + 2]);
                    mma16816(oacc[nt], ph, vfl[dg][hh], vfl[dg][hh + 2]);
                }
            }
        }
        __syncthreads();
    }

    float iA = 1.f / lA, iB = 1.f / lB;
    #pragma unroll
    for (int nt = 0; nt < 8; nt++) {
        int col = h * 64 + nt * 8 + (lane & 3) * 2;
        size_t gA = ((size_t)(b * Mseq + rowA)) * Dm + col;
        size_t gB = ((size_t)(b * Mseq + rowB)) * Dm + col;
        *(uint32_t*)&aout[gA] = pack2h(oacc[nt][0] * iA, oacc[nt][1] * iA);
        *(uint32_t*)&aout[gB] = pack2h(oacc[nt][2] * iB, oacc[nt][3] * iB);
    }
}

// ---------------------------------------------------------------------------
// Host launcher
// ---------------------------------------------------------------------------
extern "C" void kernel_launch(void* const* d_in, const int* in_sizes, int n_in,
                              void* d_out, int out_size)
{
    const int*   tokens = (const int*)  d_in[0];
    const float* emb    = (const float*)d_in[1];
    const float* pos    = (const float*)d_in[2];
    const float* ln1_s  = (const float*)d_in[3];
    const float* ln1_b  = (const float*)d_in[4];
    const float* Pi     = (const float*)d_in[5];
    const float* Po     = (const float*)d_in[6];
    const float* ln2_s  = (const float*)d_in[7];
    const float* ln2_b  = (const float*)d_in[8];
    const float* W1     = (const float*)d_in[9];
    const float* b1     = (const float*)d_in[10];
    const float* W2     = (const float*)d_in[11];
    const float* b2     = (const float*)d_in[12];
    const float* lnf_s  = (const float*)d_in[13];
    const float* lnf_b  = (const float*)d_in[14];
    const float* Wh     = (const float*)d_in[15];
    const float* bh     = (const float*)d_in[16];
    float* out = (float*)d_out;
    const int V = in_sizes[16];

    float *x;
    __half *qkvh, *qkvl, *y, *a, *hbuf;
    __half *PiTh, *PiTl, *PoTh, *PoTl, *W1Th, *W1Tl, *W2Th, *W2Tl, *WhTh;
    cudaGetSymbolAddress((void**)&x,    g_x);
    cudaGetSymbolAddress((void**)&qkvh, g_qkvh); cudaGetSymbolAddress((void**)&qkvl, g_qkvl);
    cudaGetSymbolAddress((void**)&y,    g_y);
    cudaGetSymbolAddress((void**)&a,    g_a);
    cudaGetSymbolAddress((void**)&hbuf, g_h);
    cudaGetSymbolAddress((void**)&PiTh, g_PiTh); cudaGetSymbolAddress((void**)&PiTl, g_PiTl);
    cudaGetSymbolAddress((void**)&PoTh, g_PoTh); cudaGetSymbolAddress((void**)&PoTl, g_PoTl);
    cudaGetSymbolAddress((void**)&W1Th, g_W1Th); cudaGetSymbolAddress((void**)&W1Tl, g_W1Tl);
    cudaGetSymbolAddress((void**)&W2Th, g_W2Th); cudaGetSymbolAddress((void**)&W2Tl, g_W2Tl);
    cudaGetSymbolAddress((void**)&WhTh, g_WhTh);

    cudaFuncSetAttribute(gemm_hmma<false, false, false, false, true,  false, true>,
                         cudaFuncAttributeMaxDynamicSharedMemorySize, SMEM_GEMM);
    cudaFuncSetAttribute(gemm_hmma<false, true,  false, true,  false, false, true>,
                         cudaFuncAttributeMaxDynamicSharedMemorySize, SMEM_GEMM);
    cudaFuncSetAttribute(gemm_hmma<true,  false, true,  false, false, true,  true>,
                         cudaFuncAttributeMaxDynamicSharedMemorySize, SMEM_GEMM);
    cudaFuncSetAttribute(gemm_hmma<true,  true,  false, true,  false, false, true>,
                         cudaFuncAttributeMaxDynamicSharedMemorySize, SMEM_GEMM);
    cudaFuncSetAttribute(gemm_hmma<true,  false, false, true,  false, false, false>,
                         cudaFuncAttributeMaxDynamicSharedMemorySize, SMEM_GEMM);
    cudaFuncSetAttribute(attn_tc,
                         cudaFuncAttributeMaxDynamicSharedMemorySize, SMEM_ATT);

    dim3 cblk(32, 8);
    convT_kernel<<<dim3(96, 32, Ll), cblk>>>(Pi, PiTh, PiTl, Dm, 3 * Dm,
                                             (size_t)Dm * 3 * Dm, (size_t)3 * Dm * Dm);
    convT_kernel<<<dim3(32, 32, Ll), cblk>>>(Po, PoTh, PoTl, Dm, Dm,
                                             (size_t)Dm * Dm, (size_t)Dm * Dm);
    convT_kernel<<<dim3(128, 32, Ll), cblk>>>(W1, W1Th, W1Tl, Dm, 4 * Dm,
                                              (size_t)Dm * 4 * Dm, (size_t)4 * Dm * Dm);
    convT_kernel<<<dim3(32, 128, Ll), cblk>>>(W2, W2Th, W2Tl, 4 * Dm, Dm,
                                              (size_t)4 * Dm * Dm, (size_t)4 * Dm * Dm);
    convT_kernel<<<dim3(VPAD / 32, 32, 1), cblk>>>(Wh, WhTh, nullptr, Dm, V, 0, 0);

    embed_kernel<<<NTOK, 256>>>(tokens, emb, pos, x);

    for (int l = 0; l < Ll; l++) {
        ln_kernel<<<NTOK, 256>>>(x, y, ln1_s + l * Dm, ln1_b + l * Dm);
        gemm_hmma<false, false, false, false, true, false, true>
            <<<dim3(16, 24), 128, SMEM_GEMM>>>(
            y, PiTh + (size_t)l * 3 * Dm * Dm, PiTl + (size_t)l * 3 * Dm * Dm,
            nullptr, nullptr, nullptr, qkvh, qkvl, 3 * Dm, Dm);
        attn_tc<<<dim3(8, Hh, Bn), 256, SMEM_ATT>>>(qkvh, qkvl, a);
        gemm_hmma<false, true, false, true, false, false, true>
            <<<dim3(16, 8), 128, SMEM_GEMM>>>(
            a, PoTh + (size_t)l * Dm * Dm, PoTl + (size_t)l * Dm * Dm,
            nullptr, x, x, nullptr, nullptr, Dm, Dm);
        ln_kernel<<<NTOK, 256>>>(x, y, ln2_s + l * Dm, ln2_b + l * Dm);
        gemm_hmma<true, false, true, false, false, true, true>
            <<<dim3(16, 32), 128, SMEM_GEMM>>>(
            y, W1Th + (size_t)l * 4 * Dm * Dm, W1Tl + (size_t)l * 4 * Dm * Dm,
            b1 + (size_t)l * 4 * Dm, nullptr, nullptr, hbuf, nullptr, 4 * Dm, Dm);
        gemm_hmma<true, true, false, true, false, false, true>
            <<<dim3(16, 8), 128, SMEM_GEMM>>>(
            hbuf, W2Th + (size_t)l * 4 * Dm * Dm, W2Tl + (size_t)l * 4 * Dm * Dm,
            b2 + (size_t)l * Dm, x, x, nullptr, nullptr, Dm, 4 * Dm);
    }

    ln_kernel<<<NTOK, 256>>>(x, y, lnf_s, lnf_b);
    gemm_hmma<true, false, false, true, false, false, false>
        <<<dim3(16, VPAD / 128), 128, SMEM_GEMM>>>(
        y, WhTh, nullptr, bh, nullptr, out, nullptr, nullptr, V, Dm);
}

// round 9
// speedup vs baseline: 6.2125x; 1.2554x over previous
#include <cuda_runtime.h>
#include <cuda_fp16.h>
#include <cstdint>
#include <cstddef>

// ---------------------------------------------------------------------------
// GPT-2 forward on GB300 (sm_103 base target): fp16 HMMA GEMMs
// (2-pass exact-split weights for QKV/proj, 1-pass MLP + LM head) +
// 1-pass fp16 HMMA flash attention.
// B=2, M=1024, D=1024, H=16, K=64, L=4, V=50257.
// ---------------------------------------------------------------------------

#define Bn 2
#define Mseq 1024
#define Dm 1024
#define Hh 16
#define Ll 4
#define NTOK 2048
#define VPAD 50304            // 50257 padded to multiple of 128

// ------------------------------- scratch ----------------------------------
__device__ float g_x[NTOK * Dm];                      // residual (fp32)
__device__ __half g_qkv[NTOK * 3 * Dm];               // qkv (single fp16)
__device__ __half g_y[NTOK * Dm];                     // LN out (single fp16)
__device__ __half g_a[NTOK * Dm];                     // attn out (single fp16)
__device__ __half g_h[NTOK * 4 * Dm];                 // MLP hidden (single)
// transposed weights: [N][K] K-major, fp16 (hi; lo only where 2-pass)
__device__ __half g_PiTh[Ll * 3 * Dm * Dm], g_PiTl[Ll * 3 * Dm * Dm];
__device__ __half g_PoTh[Ll * Dm * Dm],     g_PoTl[Ll * Dm * Dm];
__device__ __half g_W1Th[Ll * 4 * Dm * Dm];
__device__ __half g_W2Th[Ll * 4 * Dm * Dm];
__device__ __half g_WhTh[(size_t)VPAD * Dm];

// ----------------------------- PTX helpers --------------------------------
__device__ __forceinline__ void ldsm4(uint32_t& r0, uint32_t& r1,
                                      uint32_t& r2, uint32_t& r3, uint32_t addr)
{
    asm volatile("ldmatrix.sync.aligned.m8n8.x4.shared.b16 {%0,%1,%2,%3}, [%4];"
                 : "=r"(r0), "=r"(r1), "=r"(r2), "=r"(r3) : "r"(addr));
}
__device__ __forceinline__ void ldsm4t(uint32_t& r0, uint32_t& r1,
                                       uint32_t& r2, uint32_t& r3, uint32_t addr)
{
    asm volatile("ldmatrix.sync.aligned.m8n8.x4.trans.shared.b16 {%0,%1,%2,%3}, [%4];"
                 : "=r"(r0), "=r"(r1), "=r"(r2), "=r"(r3) : "r"(addr));
}
__device__ __forceinline__ void mma16816(float* d, const uint32_t* a,
                                         uint32_t b0, uint32_t b1)
{
    asm volatile("mma.sync.aligned.m16n8k16.row.col.f32.f16.f16.f32 "
                 "{%0,%1,%2,%3}, {%4,%5,%6,%7}, {%8,%9}, {%0,%1,%2,%3};"
                 : "+f"(d[0]), "+f"(d[1]), "+f"(d[2]), "+f"(d[3])
                 : "r"(a[0]), "r"(a[1]), "r"(a[2]), "r"(a[3]), "r"(b0), "r"(b1));
}
__device__ __forceinline__ void cp16(uint32_t sdst, const void* gsrc)
{
    asm volatile("cp.async.cg.shared.global [%0], [%1], 16;"
                 :: "r"(sdst), "l"(gsrc));
}
__device__ __forceinline__ void cp_commit() {
    asm volatile("cp.async.commit_group;");
}
__device__ __forceinline__ uint32_t pack2h(float a, float b)
{
    __half2 h = __floats2half2_rn(a, b);
    return *(uint32_t*)&h;
}
// split a pair of floats into hi/lo fp16x2 registers
__device__ __forceinline__ void split2h(float a, float b, uint32_t& hi, uint32_t& lo)
{
    __half2 h = __floats2half2_rn(a, b);
    float ra = a - __half2float(__low2half(h));
    float rb = b - __half2float(__high2half(h));
    __half2 l = __floats2half2_rn(ra, rb);
    hi = *(uint32_t*)&h;
    lo = *(uint32_t*)&l;
}

// ---------------------------------------------------------------------------
// Embedding
// ---------------------------------------------------------------------------
__global__ void embed_kernel(const int* __restrict__ tokens,
                             const float* __restrict__ emb,
                             const float* __restrict__ pos,
                             float* __restrict__ x)
{
    int idx = blockIdx.x * blockDim.x + threadIdx.x;
    int row = idx >> 8;
    int d4  = idx & 255;
    int m   = row & (Mseq - 1);
    int t   = tokens[row];
    float4 e = ((const float4*)emb)[(size_t)t * 256 + d4];
    float4 p = ((const float4*)pos)[(size_t)m * 256 + d4];
    float4 o;
    o.x = e.x + p.x; o.y = e.y + p.y; o.z = e.z + p.z; o.w = e.w + p.w;
    ((float4*)x)[idx] = o;
}

// ---------------------------------------------------------------------------
// Transpose + split: W[K,N] fp32 -> Th (+Tl if non-null) [Nrows][K] fp16.
// ---------------------------------------------------------------------------
__global__ void convT_kernel(const float* __restrict__ W,
                             __half* __restrict__ Th,
                             __half* __restrict__ Tl,
                             int K, int N, size_t wstr, size_t tstr)
{
    __shared__ float t[32][33];
    W  += (size_t)blockIdx.z * wstr;
    Th += (size_t)blockIdx.z * tstr;
    if (Tl) Tl += (size_t)blockIdx.z * tstr;
    int n0 = blockIdx.x * 32, k0 = blockIdx.y * 32;
    int tx = threadIdx.x, ty = threadIdx.y;
    #pragma unroll
    for (int i = 0; i < 32; i += 8) {
        int k = k0 + ty + i, n = n0 + tx;
        t[ty + i][tx] = (n < N) ? W[(size_t)k * N + n] : 0.f;
    }
    __syncthreads();
    const int tid = ty * 32 + tx;
    #pragma unroll
    for (int i = 0; i < 2; i++) {
        int e  = tid + i * 256;
        int n  = e >> 4;
        int kp = e & 15;
        float v0 = t[2 * kp][n], v1 = t[2 * kp + 1][n];
        uint32_t hp, lp;
        split2h(v0, v1, hp, lp);
        size_t o = (size_t)(n0 + n) * K + k0 + 2 * kp;
        *(uint32_t*)&Th[o] = hp;
        if (Tl) *(uint32_t*)&Tl[o] = lp;
    }
}

// ---------------------------------------------------------------------------
// LayerNorm -> single fp16
// ---------------------------------------------------------------------------
__device__ __forceinline__ float blockReduceSum(float val)
{
    __shared__ float sh[8];
    __shared__ float tot;
    int lane = threadIdx.x & 31, wid = threadIdx.x >> 5;
    #pragma unroll
    for (int o = 16; o; o >>= 1) val += __shfl_down_sync(0xffffffffu, val, o);
    if (!lane) sh[wid] = val;
    __syncthreads();
    if (threadIdx.x < 32) {
        float v = (threadIdx.x < 8) ? sh[threadIdx.x] : 0.f;
        #pragma unroll
        for (int o = 4; o; o >>= 1) v += __shfl_down_sync(0xffffffffu, v, o);
        if (!threadIdx.x) tot = v;
    }
    __syncthreads();
    return tot;
}

__global__ void ln_kernel(const float* __restrict__ x,
                          __half* __restrict__ y,
                          const float* __restrict__ s, const float* __restrict__ b)
{
    int row = blockIdx.x, tid = threadIdx.x;
    const float* xr = x + (size_t)row * Dm;
    float v[4];
    #pragma unroll
    for (int i = 0; i < 4; i++) v[i] = xr[tid + 256 * i];
    float mu = blockReduceSum(v[0] + v[1] + v[2] + v[3]) * (1.f / Dm);
    float sq = 0.f;
    #pragma unroll
    for (int i = 0; i < 4; i++) { float d = v[i] - mu; sq += d * d; }
    float var = blockReduceSum(sq) * (1.f / Dm);
    float rs = rsqrtf(var + 1e-5f);
    #pragma unroll
    for (int i = 0; i < 4; i++) {
        int c = tid + 256 * i;
        float val = (v[i] - mu) * rs * s[c] + b[c];
        y[(size_t)row * Dm + c] = __float2half(val);
    }
}

__device__ __forceinline__ float gelu_new(float v)
{
    float u = 0.7978845608028654f * (v + 0.044715f * v * v * v);
    return 0.5f * v * (1.f + tanhf(u));
}

// ---------------------------------------------------------------------------
// fp16 HMMA GEMM: C[M,N] = A[M,K] @ (Bh[+Bl])[N,K]^T  (A single fp16)
// CTA tile 128x128, BK=32, 128 threads (4 warps, 64x64 warp tile), 2 CTA/SM.
// PASS2: include the Bl correction pass.
// ---------------------------------------------------------------------------
#define LDB 80
#define MATB (128 * LDB)
#define STG  (3 * MATB)        // A, Bh, Bl
#define SMEM_GEMM (2 * STG)    // 61440

template <bool BIAS, bool RES, bool GELU, bool OUTF32, bool OUTH, bool PASS2>
__global__ __launch_bounds__(128, 2) void gemm_hmma(
    const __half* __restrict__ A,
    const __half* __restrict__ Bh, const __half* __restrict__ Bl,
    const float* __restrict__ bias, const float* __restrict__ Res,
    float* __restrict__ C, __half* __restrict__ Ch, int N, int K)
{
    extern __shared__ char smem[];
    const uint32_t sb = (uint32_t)__cvta_generic_to_shared(smem);
    const int tid  = threadIdx.x;
    const int lane = tid & 31;
    const int wid  = tid >> 5;
    const int bm = blockIdx.x * 128;
    const int bn = blockIdx.y * 128;
    const int wm = (wid & 1) * 64;
    const int wn = (wid >> 1) * 64;

    float acc[4][8][4];
    #pragma unroll
    for (int i = 0; i < 4; i++)
        #pragma unroll
        for (int j = 0; j < 8; j++)
            #pragma unroll
            for (int k = 0; k < 4; k++) acc[i][j][k] = 0.f;

    auto load_stage = [&](int c, int s) {
        const int kc = c * 32;
        const uint32_t st = sb + s * STG;
        #pragma unroll
        for (int i = 0; i < 4; i++) {
            int idx = tid + i * 128;          // 0..511
            int r = idx >> 2, q = idx & 3;
            uint32_t so = st + r * LDB + q * 16;
            size_t ga = (size_t)(bm + r) * K + kc + q * 8;
            cp16(so, A + ga);
            size_t gb = (size_t)(bn + r) * K + kc + q * 8;
            cp16(so + MATB, Bh + gb);
            if (PASS2) cp16(so + 2 * MATB, Bl + gb);
        }
        cp_commit();
    };

    const int nk = K / 32;
    load_stage(0, 0);

    const int lr  = lane & 15;
    const int kc2 = (lane >> 4) << 3;

    for (int c = 0; c < nk; c++) {
        const int s = c & 1;
        if (c + 1 < nk) {
            load_stage(c + 1, s ^ 1);
            asm volatile("cp.async.wait_group 1;");
        } else {
            asm volatile("cp.async.wait_group 0;");
        }
        __syncthreads();

        const uint32_t st = sb + s * STG;
        #pragma unroll
        for (int ks = 0; ks < 2; ks++) {
            const uint32_t ao = st + (wm + lr) * LDB + (ks * 16 + kc2) * 2;
            const uint32_t bo = st + MATB + (wn + lr) * LDB + (ks * 16 + kc2) * 2;
            uint32_t af[4][4], bh[4][4], bl[4][4];
            #pragma unroll
            for (int mt = 0; mt < 4; mt++)
                ldsm4(af[mt][0], af[mt][1], af[mt][2], af[mt][3], ao + mt * 16 * LDB);
            #pragma unroll
            for (int g = 0; g < 4; g++)
                ldsm4(bh[g][0], bh[g][1], bh[g][2], bh[g][3], bo + g * 16 * LDB);
            if (PASS2) {
                #pragma unroll
                for (int g = 0; g < 4; g++)
                    ldsm4(bl[g][0], bl[g][1], bl[g][2], bl[g][3],
                          bo + MATB + g * 16 * LDB);
            }

            #pragma unroll
            for (int mt = 0; mt < 4; mt++)
                #pragma unroll
                for (int nt = 0; nt < 8; nt++) {
                    int g = nt >> 1, h = nt & 1;
                    mma16816(acc[mt][nt], af[mt], bh[g][h], bh[g][2 + h]);
                    if (PASS2)
                        mma16816(acc[mt][nt], af[mt], bl[g][h], bl[g][2 + h]);
                }
        }
        __syncthreads();
    }

    const bool headN = (N & 1) != 0;
    #pragma unroll
    for (int mt = 0; mt < 4; mt++) {
        #pragma unroll
        for (int nt = 0; nt < 8; nt++) {
            int row0 = bm + wm + mt * 16 + (lane >> 2);
            int col  = bn + wn + nt * 8 + (lane & 3) * 2;
            #pragma unroll
            for (int half = 0; half < 2; half++) {
                int row = row0 + half * 8;
                float v0 = acc[mt][nt][half * 2];
                float v1 = acc[mt][nt][half * 2 + 1];
                if (!headN) {
                    size_t base = (size_t)row * N + col;
                    if (BIAS) { v0 += bias[col]; v1 += bias[col + 1]; }
                    if (GELU) { v0 = gelu_new(v0); v1 = gelu_new(v1); }
                    if (RES) {
                        float2 r = *(const float2*)&Res[base];
                        v0 += r.x; v1 += r.y;
                    }
                    if (OUTF32) {
                        float2 o; o.x = v0; o.y = v1;
                        *(float2*)&C[base] = o;
                    }
                    if (OUTH) {
                        *(uint32_t*)&Ch[base] = pack2h(v0, v1);
                    }
                } else {
                    size_t rb = (size_t)row * N;
                    if (col < N) {
                        float v = v0;
                        if (BIAS) v += bias[col];
                        C[rb + col] = v;
                    }
                    if (col + 1 < N) {
                        float v = v1;
                        if (BIAS) v += bias[col + 1];
                        C[rb + col + 1] = v;
                    }
                }
            }
        }
    }
}

// ---------------------------------------------------------------------------
// fp16 flash attention (causal), 1-pass: Q,K,V,P single fp16; fp32 softmax.
// CTA = 128 queries x one (b,h); 8 warps x 16 queries.
// ---------------------------------------------------------------------------
#define AROWB 144
#define SMEM_ATT 36864

__global__ __launch_bounds__(256) void attn_tc(
    const __half* __restrict__ qkv,
    __half* __restrict__ aout)
{
    extern __shared__ char smem[];
    const uint32_t sb = (uint32_t)__cvta_generic_to_shared(smem);
    const uint32_t sQ = sb;
    const uint32_t sK = sb + 18432, sV = sb + 27648;
    const int tid = threadIdx.x, lane = tid & 31, w = tid >> 5;
    const int qt = gridDim.x - 1 - blockIdx.x;     // big tiles first
    const int h = blockIdx.y, b = blockIdx.z;

    #pragma unroll
    for (int i = 0; i < 4; i++) {
        int idx = tid + i * 256;            // 0..1023
        int r = idx >> 3, q8 = idx & 7;
        size_t g = ((size_t)(b * Mseq + qt * 128 + r)) * 3072 + h * 192 + q8 * 8;
        cp16(sQ + r * AROWB + q8 * 16, qkv + g);
    }
    cp_commit();
    asm volatile("cp.async.wait_group 0;");
    __syncthreads();

    const int lr  = lane & 15;
    const int khi = (lane >> 4) << 3;

    uint32_t qf[4][4];
    #pragma unroll
    for (int kc = 0; kc < 4; kc++) {
        uint32_t ad = (w * 16 + lr) * AROWB + (kc * 16 + khi) * 2;
        ldsm4(qf[kc][0], qf[kc][1], qf[kc][2], qf[kc][3], sQ + ad);
    }

    float oacc[8][4];
    #pragma unroll
    for (int i = 0; i < 8; i++)
        #pragma unroll
        for (int j = 0; j < 4; j++) oacc[i][j] = 0.f;
    float mA = -1e30f, mB = -1e30f, lA = 0.f, lB = 0.f;

    const int q0   = qt * 128 + w * 16;
    const int rowA = q0 + (lane >> 2);
    const int rowB = rowA + 8;

    const int nkt = 2 * qt + 2;
    for (int kt = 0; kt < nkt; kt++) {
        #pragma unroll
        for (int i = 0; i < 2; i++) {
            int idx = tid + i * 256;        // 0..511
            int r = idx >> 3, q8 = idx & 7;
            size_t base = ((size_t)(b * Mseq + kt * 64 + r)) * 3072 + h * 192;
            uint32_t sd = r * AROWB + q8 * 16;
            cp16(sK + sd, qkv + base + 64  + q8 * 8);
            cp16(sV + sd, qkv + base + 128 + q8 * 8);
        }
        cp_commit();
        asm volatile("cp.async.wait_group 0;");
        __syncthreads();

        if (kt * 64 <= q0 + 15) {
            float sacc[8][4];
            #pragma unroll
            for (int i = 0; i < 8; i++)
                #pragma unroll
                for (int j = 0; j < 4; j++) sacc[i][j] = 0.f;

            #pragma unroll
            for (int kc = 0; kc < 4; kc++) {
                uint32_t kf[4][4];
                #pragma unroll
                for (int g = 0; g < 4; g++) {
                    uint32_t ad = (g * 16 + lr) * AROWB + (kc * 16 + khi) * 2;
                    ldsm4(kf[g][0], kf[g][1], kf[g][2], kf[g][3], sK + ad);
                }
                #pragma unroll
                for (int nt = 0; nt < 8; nt++) {
                    int g = nt >> 1, hh = nt & 1;
                    mma16816(sacc[nt], qf[kc], kf[g][hh], kf[g][2 + hh]);
                }
            }

            float mxA = -1e30f, mxB = -1e30f;
            #pragma unroll
            for (int nt = 0; nt < 8; nt++) {
                int k0 = kt * 64 + nt * 8 + (lane & 3) * 2;
                float s0 = sacc[nt][0] * 0.125f;
                float s1 = sacc[nt][1] * 0.125f;
                float s2 = sacc[nt][2] * 0.125f;
                float s3 = sacc[nt][3] * 0.125f;
                if (k0     > rowA) s0 = -1e30f;
                if (k0 + 1 > rowA) s1 = -1e30f;
                if (k0     > rowB) s2 = -1e30f;
                if (k0 + 1 > rowB) s3 = -1e30f;
                sacc[nt][0] = s0; sacc[nt][1] = s1;
                sacc[nt][2] = s2; sacc[nt][3] = s3;
                mxA = fmaxf(mxA, fmaxf(s0, s1));
                mxB = fmaxf(mxB, fmaxf(s2, s3));
            }
            mxA = fmaxf(mxA, __shfl_xor_sync(0xffffffffu, mxA, 1));
            mxA = fmaxf(mxA, __shfl_xor_sync(0xffffffffu, mxA, 2));
            mxB = fmaxf(mxB, __shfl_xor_sync(0xffffffffu, mxB, 1));
            mxB = fmaxf(mxB, __shfl_xor_sync(0xffffffffu, mxB, 2));
            float mnA = fmaxf(mA, mxA), mnB = fmaxf(mB, mxB);
            float cA = __expf(mA - mnA), cB = __expf(mB - mnB);
            mA = mnA; mB = mnB;

            float sA = 0.f, sB = 0.f;
            #pragma unroll
            for (int nt = 0; nt < 8; nt++) {
                sacc[nt][0] = __expf(sacc[nt][0] - mnA);
                sacc[nt][1] = __expf(sacc[nt][1] - mnA);
                sacc[nt][2] = __expf(sacc[nt][2] - mnB);
                sacc[nt][3] = __expf(sacc[nt][3] - mnB);
                sA += sacc[nt][0] + sacc[nt][1];
                sB += sacc[nt][2] + sacc[nt][3];
            }
            sA += __shfl_xor_sync(0xffffffffu, sA, 1);
            sA += __shfl_xor_sync(0xffffffffu, sA, 2);
            sB += __shfl_xor_sync(0xffffffffu, sB, 1);
            sB += __shfl_xor_sync(0xffffffffu, sB, 2);
            lA = lA * cA + sA;
            lB = lB * cB + sB;
            #pragma unroll
            for (int nt = 0; nt < 8; nt++) {
                oacc[nt][0] *= cA; oacc[nt][1] *= cA;
                oacc[nt][2] *= cB; oacc[nt][3] *= cB;
            }

            #pragma unroll
            for (int kc = 0; kc < 4; kc++) {
                uint32_t ph[4];
                ph[0] = pack2h(sacc[2 * kc][0],     sacc[2 * kc][1]);
                ph[1] = pack2h(sacc[2 * kc][2],     sacc[2 * kc][3]);
                ph[2] = pack2h(sacc[2 * kc + 1][0], sacc[2 * kc + 1][1]);
                ph[3] = pack2h(sacc[2 * kc + 1][2], sacc[2 * kc + 1][3]);

                uint32_t vf[4][4];
                #pragma unroll
                for (int dg = 0; dg < 4; dg++) {
                    uint32_t ad = (kc * 16 + (lane & 7) + ((lane >> 4) << 3)) * AROWB
                                + (dg * 16 + ((lane >> 3) & 1) * 8) * 2;
                    ldsm4t(vf[dg][0], vf[dg][1], vf[dg][2], vf[dg][3], sV + ad);
                }
                #pragma unroll
                for (int nt = 0; nt < 8; nt++) {
                    int dg = nt >> 1, hh = nt & 1;
                    mma16816(oacc[nt], ph, vf[dg][hh], vf[dg][hh + 2]);
                }
            }
        }
        __syncthreads();
    }

    float iA = 1.f / lA, iB = 1.f / lB;
    #pragma unroll
    for (int nt = 0; nt < 8; nt++) {
        int col = h * 64 + nt * 8 + (lane & 3) * 2;
        size_t gA = ((size_t)(b * Mseq + rowA)) * Dm + col;
        size_t gB = ((size_t)(b * Mseq + rowB)) * Dm + col;
        *(uint32_t*)&aout[gA] = pack2h(oacc[nt][0] * iA, oacc[nt][1] * iA);
        *(uint32_t*)&aout[gB] = pack2h(oacc[nt][2] * iB, oacc[nt][3] * iB);
    }
}

// ---------------------------------------------------------------------------
// Host launcher
// ---------------------------------------------------------------------------
extern "C" void kernel_launch(void* const* d_in, const int* in_sizes, int n_in,
                              void* d_out, int out_size)
{
    const int*   tokens = (const int*)  d_in[0];
    const float* emb    = (const float*)d_in[1];
    const float* pos    = (const float*)d_in[2];
    const float* ln1_s  = (const float*)d_in[3];
    const float* ln1_b  = (const float*)d_in[4];
    const float* Pi     = (const float*)d_in[5];
    const float* Po     = (const float*)d_in[6];
    const float* ln2_s  = (const float*)d_in[7];
    const float* ln2_b  = (const float*)d_in[8];
    const float* W1     = (const float*)d_in[9];
    const float* b1     = (const float*)d_in[10];
    const float* W2     = (const float*)d_in[11];
    const float* b2     = (const float*)d_in[12];
    const float* lnf_s  = (const float*)d_in[13];
    const float* lnf_b  = (const float*)d_in[14];
    const float* Wh     = (const float*)d_in[15];
    const float* bh     = (const float*)d_in[16];
    float* out = (float*)d_out;
    const int V = in_sizes[16];

    float *x;
    __half *qkv, *y, *a, *hbuf;
    __half *PiTh, *PiTl, *PoTh, *PoTl, *W1Th, *W2Th, *WhTh;
    cudaGetSymbolAddress((void**)&x,    g_x);
    cudaGetSymbolAddress((void**)&qkv,  g_qkv);
    cudaGetSymbolAddress((void**)&y,    g_y);
    cudaGetSymbolAddress((void**)&a,    g_a);
    cudaGetSymbolAddress((void**)&hbuf, g_h);
    cudaGetSymbolAddress((void**)&PiTh, g_PiTh); cudaGetSymbolAddress((void**)&PiTl, g_PiTl);
    cudaGetSymbolAddress((void**)&PoTh, g_PoTh); cudaGetSymbolAddress((void**)&PoTl, g_PoTl);
    cudaGetSymbolAddress((void**)&W1Th, g_W1Th);
    cudaGetSymbolAddress((void**)&W2Th, g_W2Th);
    cudaGetSymbolAddress((void**)&WhTh, g_WhTh);

    cudaFuncSetAttribute(gemm_hmma<false, false, false, false, true,  true>,
                         cudaFuncAttributeMaxDynamicSharedMemorySize, SMEM_GEMM);
    cudaFuncSetAttribute(gemm_hmma<false, true,  false, true,  false, true>,
                         cudaFuncAttributeMaxDynamicSharedMemorySize, SMEM_GEMM);
    cudaFuncSetAttribute(gemm_hmma<true,  false, true,  false, true,  false>,
                         cudaFuncAttributeMaxDynamicSharedMemorySize, SMEM_GEMM);
    cudaFuncSetAttribute(gemm_hmma<true,  true,  false, true,  false, false>,
                         cudaFuncAttributeMaxDynamicSharedMemorySize, SMEM_GEMM);
    cudaFuncSetAttribute(gemm_hmma<true,  false, false, true,  false, false>,
                         cudaFuncAttributeMaxDynamicSharedMemorySize, SMEM_GEMM);
    cudaFuncSetAttribute(attn_tc,
                         cudaFuncAttributeMaxDynamicSharedMemorySize, SMEM_ATT);

    dim3 cblk(32, 8);
    convT_kernel<<<dim3(96, 32, Ll), cblk>>>(Pi, PiTh, PiTl, Dm, 3 * Dm,
                                             (size_t)Dm * 3 * Dm, (size_t)3 * Dm * Dm);
    convT_kernel<<<dim3(32, 32, Ll), cblk>>>(Po, PoTh, PoTl, Dm, Dm,
                                             (size_t)Dm * Dm, (size_t)Dm * Dm);
    convT_kernel<<<dim3(128, 32, Ll), cblk>>>(W1, W1Th, nullptr, Dm, 4 * Dm,
                                              (size_t)Dm * 4 * Dm, (size_t)4 * Dm * Dm);
    convT_kernel<<<dim3(32, 128, Ll), cblk>>>(W2, W2Th, nullptr, 4 * Dm, Dm,
                                              (size_t)4 * Dm * Dm, (size_t)4 * Dm * Dm);
    convT_kernel<<<dim3(VPAD / 32, 32, 1), cblk>>>(Wh, WhTh, nullptr, Dm, V, 0, 0);

    embed_kernel<<<NTOK, 256>>>(tokens, emb, pos, x);

    for (int l = 0; l < Ll; l++) {
        ln_kernel<<<NTOK, 256>>>(x, y, ln1_s + l * Dm, ln1_b + l * Dm);
        gemm_hmma<false, false, false, false, true, true>
            <<<dim3(16, 24), 128, SMEM_GEMM>>>(
            y, PiTh + (size_t)l * 3 * Dm * Dm, PiTl + (size_t)l * 3 * Dm * Dm,
            nullptr, nullptr, nullptr, qkv, 3 * Dm, Dm);
        attn_tc<<<dim3(8, Hh, Bn), 256, SMEM_ATT>>>(qkv, a);
        gemm_hmma<false, true, false, true, false, true>
            <<<dim3(16, 8), 128, SMEM_GEMM>>>(
            a, PoTh + (size_t)l * Dm * Dm, PoTl + (size_t)l * Dm * Dm,
            nullptr, x, x, nullptr, Dm, Dm);
        ln_kernel<<<NTOK, 256>>>(x, y, ln2_s + l * Dm, ln2_b + l * Dm);
        gemm_hmma<true, false, true, false, true, false>
            <<<dim3(16, 32), 128, SMEM_GEMM>>>(
            y, W1Th + (size_t)l * 4 * Dm * Dm, nullptr,
            b1 + (size_t)l * 4 * Dm, nullptr, nullptr, hbuf, 4 * Dm, Dm);
        gemm_hmma<true, true, false, true, false, false>
            <<<dim3(16, 8), 128, SMEM_GEMM>>>(
            hbuf, W2Th + (size_t)l * 4 * Dm * Dm, nullptr,
            b2 + (size_t)l * Dm, x, x, nullptr, Dm, 4 * Dm);
    }

    ln_kernel<<<NTOK, 256>>>(x, y, lnf_s, lnf_b);
    gemm_hmma<true, false, false, true, false, false>
        <<<dim3(16, VPAD / 128), 128, SMEM_GEMM>>>(
        y, WhTh, nullptr, bh, nullptr, out, nullptr, V, Dm);
}